// round 12
// baseline (speedup 1.0000x reference)
#include <cuda_runtime.h>
#include <cuda_fp16.h>
#include <cstdint>
#include <math.h>

typedef unsigned long long ull;
typedef unsigned int u32;

// ======================= problem constants =======================
#define BATCH   2
#define SEQ     2048
#define EMB     2048
#define NHEAD   32
#define HDIM    64
#define BT      (BATCH*SEQ)      // 4096
#define N_QKV   (3*EMB)          // 6144
#define KP      2048             // plain fp16 GEMM K

// ======================= scratch (device globals) ================
__device__ __half g_qkvh[(size_t)BT * N_QKV];          // qkv fp16
__device__ __half g_qh[(size_t)BATCH*NHEAD*SEQ*HDIM];  // [b,h,t,d] (scaled)
__device__ __half g_kh[(size_t)BATCH*NHEAD*SEQ*HDIM];  // [b,h,t,d]
__device__ __half g_vt[(size_t)BATCH*NHEAD*HDIM*SEQ];  // [b,h,d,t] transposed
__device__ __half g_Ax  [(size_t)BT * KP];             // x fp16
__device__ __half g_Aao [(size_t)BT * KP];             // attn-out fp16
__device__ __half g_Bqkv[(size_t)N_QKV * KP];          // Wqkv^T fp16
__device__ __half g_Bout[(size_t)EMB * KP];            // Wout^T fp16
__device__ float  g_rope[(size_t)SEQ * 32];            // [t][0:16)=cos, [t][16:32)=sin

// ======================= helpers =================================
__device__ __forceinline__ u32 smem_u32(const void* p){
    u32 a; asm("{ .reg .u64 t; cvta.to.shared.u64 t, %1; cvt.u32.u64 %0, t; }" : "=r"(a) : "l"(p));
    return a;
}
#define SWZ128(off) ((off) ^ (((off) >> 3) & 0x70))

__device__ __forceinline__ void cpasync16(u32 daddr, const void* gptr){
    asm volatile("cp.async.cg.shared.global [%0], [%1], 16;" :: "r"(daddr), "l"(gptr));
}
#define CP_COMMIT() asm volatile("cp.async.commit_group;")
#define CP_WAIT(n)  asm volatile("cp.async.wait_group %0;" :: "n"(n))

__device__ __forceinline__ void ldsm4(u32* r, u32 addr){
    asm volatile("ldmatrix.sync.aligned.m8n8.x4.shared.b16 {%0,%1,%2,%3}, [%4];"
        : "=r"(r[0]), "=r"(r[1]), "=r"(r[2]), "=r"(r[3]) : "r"(addr));
}
__device__ __forceinline__ void mma16816h(float* c, const u32* a, u32 b0, u32 b1){
    asm volatile("mma.sync.aligned.m16n8k16.row.col.f32.f16.f16.f32 "
        "{%0,%1,%2,%3}, {%4,%5,%6,%7}, {%8,%9}, {%0,%1,%2,%3};"
        : "+f"(c[0]), "+f"(c[1]), "+f"(c[2]), "+f"(c[3])
        : "r"(a[0]), "r"(a[1]), "r"(a[2]), "r"(a[3]), "r"(b0), "r"(b1));
}
// pack two fp32 -> f16x2 register: lo half = a, hi half = b
__device__ __forceinline__ u32 h2pack(float a, float b){
    u32 r;
    asm("cvt.rn.f16x2.f32 %0, %2, %1;" : "=r"(r) : "f"(a), "f"(b));
    return r;
}

// =============================================================================
// Setup: RoPE cos/sin table  [t][i] for i<16
// =============================================================================
__global__ void rope_table(float* __restrict__ T)
{
    const int idx = blockIdx.x*blockDim.x + threadIdx.x;   // 0..32767
    if (idx >= SEQ*16) return;
    const int t = idx >> 4, i = idx & 15;
    const float invf = expf(-(float)i * (9.210340371976184f / 16.0f));
    float sn, cs; sincosf((float)t * invf, &sn, &cs);
    T[t*32 + i]      = cs;
    T[t*32 + 16 + i] = sn;
}

// =============================================================================
// Conversions
// =============================================================================
// rows [R, 2048] fp32 -> fp16
__global__ void conv_rows(const float* __restrict__ X, __half* __restrict__ Ap, int R)
{
    size_t idx = (size_t)blockIdx.x*blockDim.x + threadIdx.x;
    if (idx >= (size_t)R*512) return;
    float4 x = *(const float4*)(X + idx*4);
    __half h[4] = { __float2half_rn(x.x), __float2half_rn(x.y),
                    __float2half_rn(x.z), __float2half_rn(x.w) };
    *(ull*)(Ap + idx*4) = *(const ull*)h;
}

// W [2048, N] fp32 -> Bp [N, 2048] fp16 (transpose)
__global__ void conv_BT(const float* __restrict__ W, __half* __restrict__ Bp, int N)
{
    __shared__ float tile[32][33];
    const int n0 = blockIdx.x*32, k0 = blockIdx.y*32;
    const int tx = threadIdx.x, ty = threadIdx.y;
    #pragma unroll
    for (int j=0;j<4;j++)
        tile[ty*4+j][tx] = W[(size_t)(k0+ty*4+j)*N + n0 + tx];
    __syncthreads();
    #pragma unroll
    for (int j=0;j<4;j++)
        Bp[(size_t)(n0+ty*4+j)*KP + k0 + tx] = __float2half_rn(tile[tx][ty*4+j]);
}

// =============================================================================
// HMMA GEMM (fp16, K=2048): C[M,N] = A[M,KP] * B[N,KP]^T + bias
// 128x256 CTA, 16 warps 4x4, warp 32x64, 3-stage cp.async ring, GK=64.
// Output type templated: fp32 (final) or fp16 (qkv intermediate).
// =============================================================================
#define GK 64
#define NC (KP/GK)              // 32
#define STAGE_A 16384
#define STAGE_B 32768
#define STAGE   (STAGE_A + STAGE_B)
#define NSTG 3
#define GEMM_SMEM (NSTG*STAGE)

template<typename OT>
__global__ __launch_bounds__(512, 1)
void gemm_hmma(const __half* __restrict__ A,
               const __half* __restrict__ B,
               const float* __restrict__ bias,
               OT* __restrict__ C, int N)
{
    extern __shared__ char smem[];
    const u32 sb = smem_u32(smem);
    const int tid  = threadIdx.x;
    const int wid  = tid >> 5;
    const int lane = tid & 31;
    const int wm = wid & 3;
    const int wn = wid >> 2;
    const int m0 = blockIdx.y * 128;
    const int n0 = blockIdx.x * 256;

    const __half* Ab = A + (size_t)m0 * KP;
    const __half* Bb = B + (size_t)n0 * KP;

    const int alr = tid >> 2;
    const int alk = (tid & 3) * 2;
    const int blr = tid >> 1;
    const int blk = (tid & 1) * 4;
    auto load_stage = [&](int kc, u32 off){
        const __half* Ag = Ab + (size_t)alr*KP + kc*GK + alk*8;
        #pragma unroll
        for (int j=0;j<2;j++)
            cpasync16(sb + off + SWZ128(alr*128 + (alk+j)*16), Ag + j*8);
        const __half* Bg = Bb + (size_t)blr*KP + kc*GK + blk*8;
        #pragma unroll
        for (int j=0;j<4;j++)
            cpasync16(sb + off + STAGE_A + SWZ128(blr*128 + (blk+j)*16), Bg + j*8);
    };

    float acc[2][8][4];
    #pragma unroll
    for (int a=0;a<2;a++)
        #pragma unroll
        for (int b=0;b<8;b++)
            #pragma unroll
            for (int c=0;c<4;c++) acc[a][b][c] = 0.f;

    load_stage(0, 0);       CP_COMMIT();
    load_stage(1, STAGE);   CP_COMMIT();

    const int arow = wm*32 + (lane & 15);
    const int akof = (lane >> 4) * 8;
    const int brow = wn*64 + ((lane >> 4) & 1)*8 + (lane & 7);
    const int bkof = ((lane >> 3) & 1) * 8;

    int slot = 0;
    for (int i=0; i<NC; i++){
        CP_WAIT(1);
        __syncthreads();

        if (i+2 < NC){
            int ns = slot + 2; if (ns >= NSTG) ns -= NSTG;
            load_stage(i+2, (u32)ns * STAGE);
        }
        CP_COMMIT();

        const u32 abase = sb + (u32)slot * STAGE;
        const u32 bbase = abase + STAGE_A;

        #pragma unroll
        for (int ks=0; ks<4; ks++){
            const int k0 = ks*16;
            u32 afr[2][4];
            #pragma unroll
            for (int mf=0; mf<2; mf++)
                ldsm4(afr[mf], abase + SWZ128((arow + mf*16)*128 + (k0 + akof)*2));
            u32 bfr[4][4];
            #pragma unroll
            for (int nq=0; nq<4; nq++)
                ldsm4(bfr[nq], bbase + SWZ128((brow + nq*16)*128 + (k0 + bkof)*2));
            #pragma unroll
            for (int mf=0; mf<2; mf++)
                #pragma unroll
                for (int nq=0; nq<4; nq++){
                    mma16816h(acc[mf][nq*2+0], afr[mf], bfr[nq][0], bfr[nq][1]);
                    mma16816h(acc[mf][nq*2+1], afr[mf], bfr[nq][2], bfr[nq][3]);
                }
        }
        slot++; if (slot >= NSTG) slot = 0;
    }

    #pragma unroll
    for (int mf=0; mf<2; mf++){
        const int r = m0 + wm*32 + mf*16 + (lane >> 2);
        #pragma unroll
        for (int nf=0; nf<8; nf++){
            const int c = n0 + wn*64 + nf*8 + (lane & 3)*2;
            const float b0 = bias[c], b1 = bias[c+1];
            OT* cp = C + (size_t)r*N + c;
            if constexpr (sizeof(OT) == 2){
                *(u32*)cp = h2pack(acc[mf][nf][0] + b0, acc[mf][nf][1] + b1);
                *(u32*)(cp + 8*(size_t)N) = h2pack(acc[mf][nf][2] + b0, acc[mf][nf][3] + b1);
            } else {
                *(float2*)cp = make_float2(acc[mf][nf][0] + b0, acc[mf][nf][1] + b1);
                *(float2*)(cp + 8*(size_t)N) = make_float2(acc[mf][nf][2] + b0, acc[mf][nf][3] + b1);
            }
        }
    }
}

// =============================================================================
// RoPE (table) + scatter: fp16 qkv -> qh/kh [b,h,t,d], vt [b,h,d,t]
// =============================================================================
__global__ void rope_scatter(const __half* __restrict__ qkv,
                             const float* __restrict__ T,
                             __half* __restrict__ qh, __half* __restrict__ kh,
                             __half* __restrict__ vt)
{
    const int bt = blockIdx.x;
    const int b = bt >> 11, t = bt & 2047;
    const __half* row = qkv + (size_t)bt * N_QKV;
    const float* Tc = T + t*32;

    for (int e = threadIdx.x; e < EMB; e += blockDim.x){
        const int h = e >> 6, d = e & 63;
        const size_t dst = ((size_t)(b*NHEAD + h) * SEQ + t) * HDIM + d;
        float qv = __half2float(row[e]);
        float kv = __half2float(row[EMB + e]);
        const __half vv = row[2*EMB + e];
        if (d < 32){
            const int i = d & 15;
            const float cs = Tc[i], sn = Tc[16 + i];
            if (d < 16){
                const float qx2 = __half2float(row[e + 16]);
                const float kx2 = __half2float(row[EMB + e + 16]);
                qv = qv*cs - qx2*sn;
                kv = kv*cs - kx2*sn;
            } else {
                const float qx1 = __half2float(row[e - 16]);
                const float kx1 = __half2float(row[EMB + e - 16]);
                qv = qx1*sn + qv*cs;
                kv = kx1*sn + kv*cs;
            }
        }
        qh[dst] = __float2half(qv * 0.125f);
        kh[dst] = __float2half(kv);
        vt[((size_t)(b*NHEAD + h) * HDIM + d) * SEQ + t] = vv;
    }
}

// =============================================================================
// Flash attention, fp16 HMMA, causal. Epilogue writes fp16 Aao [BT, 2048].
// =============================================================================
#define FA_KV   16384
#define FA_SMEM (16384 + 3*FA_KV)        // 64 KB

__global__ __launch_bounds__(256, 2)
void flash_hmma(const __half* __restrict__ Qh, const __half* __restrict__ Kh,
                const __half* __restrict__ Vt, __half* __restrict__ Aao)
{
    extern __shared__ char smem[];
    const u32 sb = smem_u32(smem);
    const int tid = threadIdx.x, wid = tid >> 5, lane = tid & 31;
    const int qt = (int)gridDim.x - 1 - (int)blockIdx.x;   // heavy tiles first
    const int bh = blockIdx.y;
    const size_t base = (size_t)bh * SEQ * HDIM;
    const int nkt = 2*qt + 2;

    {
        const int r = tid >> 1;
        const int g = (tid & 1) * 4;
        const __half* Qg = Qh + base + (size_t)(qt*128 + r)*HDIM + g*8;
        #pragma unroll
        for (int j=0;j<4;j++)
            cpasync16(sb + SWZ128(r*128 + (g+j)*16), Qg + j*8);
    }
    const int kvr = tid >> 2;
    const int kvg = (tid & 3) * 2;
    auto load_kv = [&](int kt, u32 off){
        const __half* Kg = Kh + base + (size_t)(kt*64 + kvr)*HDIM + kvg*8;
        cpasync16(sb + off        + SWZ128(kvr*128 +  kvg   *16), Kg);
        cpasync16(sb + off        + SWZ128(kvr*128 + (kvg+1)*16), Kg + 8);
        const __half* Vg = Vt + base + (size_t)kvr*SEQ + kt*64 + kvg*8;
        cpasync16(sb + off + 8192 + SWZ128(kvr*128 +  kvg   *16), Vg);
        cpasync16(sb + off + 8192 + SWZ128(kvr*128 + (kvg+1)*16), Vg + 8);
    };

    load_kv(0, 16384);              CP_COMMIT();
    if (nkt > 1) load_kv(1, 16384 + FA_KV);
    CP_COMMIT();

    CP_WAIT(1);
    __syncthreads();

    u32 aq[4][4];
    {
        const int arow = wid*16 + (lane & 15);
        const int akof = (lane >> 4) * 8;
        #pragma unroll
        for (int ks=0; ks<4; ks++)
            ldsm4(aq[ks], sb + SWZ128(arow*128 + (ks*16 + akof)*2));
    }

    const int brow = ((lane >> 4) & 1)*8 + (lane & 7);
    const int bkof = ((lane >> 3) & 1) * 8;
    const int rq   = qt*128 + wid*16 + (lane >> 2);

    float oacc[8][4];
    #pragma unroll
    for (int j=0;j<8;j++){ oacc[j][0]=0.f; oacc[j][1]=0.f; oacc[j][2]=0.f; oacc[j][3]=0.f; }
    float m0 = -1e30f, m1 = -1e30f, l0 = 0.f, l1 = 0.f;

    int slot = 0;
    for (int kt = 0; kt < nkt; kt++){
        if (kt > 0){ CP_WAIT(1); __syncthreads(); }
        if (kt+2 < nkt){
            int ns = slot + 2; if (ns >= 3) ns -= 3;
            load_kv(kt+2, 16384 + (u32)ns*FA_KV);
        }
        CP_COMMIT();

        const u32 kbase = sb + 16384 + (u32)slot*FA_KV;
        const u32 vbase = kbase + 8192;

        float sacc[8][4];
        #pragma unroll
        for (int j=0;j<8;j++){ sacc[j][0]=0.f; sacc[j][1]=0.f; sacc[j][2]=0.f; sacc[j][3]=0.f; }
        #pragma unroll
        for (int ks=0; ks<4; ks++){
            #pragma unroll
            for (int nq=0; nq<4; nq++){
                u32 bfr[4];
                ldsm4(bfr, kbase + SWZ128((nq*16 + brow)*128 + (ks*16 + bkof)*2));
                mma16816h(sacc[nq*2+0], aq[ks], bfr[0], bfr[1]);
                mma16816h(sacc[nq*2+1], aq[ks], bfr[2], bfr[3]);
            }
        }

        if (kt >= 2*qt){
            #pragma unroll
            for (int j=0;j<8;j++){
                const int c = kt*64 + (j>>1)*16 + ((j&1)<<3) + ((lane&3)<<1);
                if (c   > rq)   sacc[j][0] = -1e30f;
                if (c+1 > rq)   sacc[j][1] = -1e30f;
                if (c   > rq+8) sacc[j][2] = -1e30f;
                if (c+1 > rq+8) sacc[j][3] = -1e30f;
            }
        }

        float mx0 = -1e30f, mx1 = -1e30f;
        #pragma unroll
        for (int j=0;j<8;j++){
            mx0 = fmaxf(mx0, fmaxf(sacc[j][0], sacc[j][1]));
            mx1 = fmaxf(mx1, fmaxf(sacc[j][2], sacc[j][3]));
        }
        mx0 = fmaxf(mx0, __shfl_xor_sync(0xffffffffu, mx0, 1));
        mx0 = fmaxf(mx0, __shfl_xor_sync(0xffffffffu, mx0, 2));
        mx1 = fmaxf(mx1, __shfl_xor_sync(0xffffffffu, mx1, 1));
        mx1 = fmaxf(mx1, __shfl_xor_sync(0xffffffffu, mx1, 2));
        const float mn0 = fmaxf(m0, mx0), mn1 = fmaxf(m1, mx1);
        const float cr0 = __expf(m0 - mn0), cr1 = __expf(m1 - mn1);
        m0 = mn0; m1 = mn1;
        float rs0 = 0.f, rs1 = 0.f;
        #pragma unroll
        for (int j=0;j<8;j++){
            sacc[j][0] = __expf(sacc[j][0] - mn0); rs0 += sacc[j][0];
            sacc[j][1] = __expf(sacc[j][1] - mn0); rs0 += sacc[j][1];
            sacc[j][2] = __expf(sacc[j][2] - mn1); rs1 += sacc[j][2];
            sacc[j][3] = __expf(sacc[j][3] - mn1); rs1 += sacc[j][3];
        }
        rs0 += __shfl_xor_sync(0xffffffffu, rs0, 1);
        rs0 += __shfl_xor_sync(0xffffffffu, rs0, 2);
        rs1 += __shfl_xor_sync(0xffffffffu, rs1, 1);
        rs1 += __shfl_xor_sync(0xffffffffu, rs1, 2);
        l0 = l0*cr0 + rs0;
        l1 = l1*cr1 + rs1;
        #pragma unroll
        for (int j=0;j<8;j++){
            oacc[j][0] *= cr0; oacc[j][1] *= cr0;
            oacc[j][2] *= cr1; oacc[j][3] *= cr1;
        }

        #pragma unroll
        for (int kc=0; kc<4; kc++){
            u32 ap[4];
            ap[0] = h2pack(sacc[2*kc  ][0], sacc[2*kc  ][1]);
            ap[1] = h2pack(sacc[2*kc  ][2], sacc[2*kc  ][3]);
            ap[2] = h2pack(sacc[2*kc+1][0], sacc[2*kc+1][1]);
            ap[3] = h2pack(sacc[2*kc+1][2], sacc[2*kc+1][3]);
            #pragma unroll
            for (int nq=0; nq<4; nq++){
                u32 bfr[4];
                ldsm4(bfr, vbase + SWZ128((nq*16 + brow)*128 + (kc*16 + bkof)*2));
                mma16816h(oacc[nq*2+0], ap, bfr[0], bfr[1]);
                mma16816h(oacc[nq*2+1], ap, bfr[2], bfr[3]);
            }
        }
        slot++; if (slot >= 3) slot = 0;
    }

    // ---- epilogue: normalize, write fp16 Aao [b*SEQ+t][2048]
    const float inv0 = 1.f / l0, inv1 = 1.f / l1;
    const int b = bh >> 5, h = bh & 31;
    const int t0 = qt*128 + wid*16 + (lane >> 2);
    __half* a0 = Aao + ((size_t)(b*SEQ + t0))*EMB + h*64;
    __half* a1 = a0 + 8*(size_t)EMB;
    #pragma unroll
    for (int j=0;j<8;j++){
        const int c = (j>>1)*16 + ((j&1)<<3) + ((lane&3)<<1);
        *(u32*)(a0 + c) = h2pack(oacc[j][0]*inv0, oacc[j][1]*inv0);
        *(u32*)(a1 + c) = h2pack(oacc[j][2]*inv1, oacc[j][3]*inv1);
    }
}

// =============================================================================
extern "C" void kernel_launch(void* const* d_in, const int* in_sizes, int n_in,
                              void* d_out, int out_size)
{
    (void)in_sizes; (void)n_in; (void)out_size;
    const float* x    = (const float*)d_in[0];
    const float* Wqkv = (const float*)d_in[1];
    const float* bqkv = (const float*)d_in[2];
    const float* Wout = (const float*)d_in[3];
    const float* bout = (const float*)d_in[4];
    float* out = (float*)d_out;

    __half *qkvh, *qh, *kh, *vt, *Ax, *Aao, *Bqkv, *Bout;
    float* rope;
    cudaGetSymbolAddress((void**)&qkvh, g_qkvh);
    cudaGetSymbolAddress((void**)&qh,  g_qh);
    cudaGetSymbolAddress((void**)&kh,  g_kh);
    cudaGetSymbolAddress((void**)&vt,  g_vt);
    cudaGetSymbolAddress((void**)&Ax,   g_Ax);
    cudaGetSymbolAddress((void**)&Aao,  g_Aao);
    cudaGetSymbolAddress((void**)&Bqkv, g_Bqkv);
    cudaGetSymbolAddress((void**)&Bout, g_Bout);
    cudaGetSymbolAddress((void**)&rope, g_rope);

    cudaFuncSetAttribute(gemm_hmma<__half>, cudaFuncAttributeMaxDynamicSharedMemorySize, GEMM_SMEM);
    cudaFuncSetAttribute(gemm_hmma<float>,  cudaFuncAttributeMaxDynamicSharedMemorySize, GEMM_SMEM);
    cudaFuncSetAttribute(flash_hmma, cudaFuncAttributeMaxDynamicSharedMemorySize, FA_SMEM);

    // 0) setup + fp16 conversions
    rope_table<<<(SEQ*16 + 255)/256, 256>>>(rope);
    conv_rows<<<(BT*512 + 255)/256, 256>>>(x, Ax, BT);
    conv_BT<<<dim3(N_QKV/32, EMB/32), dim3(32,8)>>>(Wqkv, Bqkv, N_QKV);
    conv_BT<<<dim3(EMB/32,  EMB/32), dim3(32,8)>>>(Wout, Bout, EMB);

    // 1) QKV projection (fp16 HMMA, fp16 output)
    gemm_hmma<__half><<<dim3(N_QKV/256, BT/128), 512, GEMM_SMEM>>>(Ax, Bqkv, bqkv, qkvh, N_QKV);

    // 2) RoPE (table) + scatter to fp16 (V transposed)
    rope_scatter<<<BT, 256>>>(qkvh, rope, qh, kh, vt);

    // 3) causal flash attention (fp16 tensor cores); writes fp16 Aao
    flash_hmma<<<dim3(SEQ/128, BATCH*NHEAD), 256, FA_SMEM>>>(qh, kh, vt, Aao);

    // 4) output projection (fp16 HMMA, fp32 output)
    gemm_hmma<float><<<dim3(EMB/256, BT/128), 512, GEMM_SMEM>>>(Aao, Bout, bout, out, EMB);
}

// round 13
// speedup vs baseline: 1.0417x; 1.0417x over previous
#include <cuda_runtime.h>
#include <cuda_fp16.h>
#include <cstdint>
#include <math.h>

typedef unsigned long long ull;
typedef unsigned int u32;

// ======================= problem constants =======================
#define BATCH   2
#define SEQ     2048
#define EMB     2048
#define NHEAD   32
#define HDIM    64
#define BT      (BATCH*SEQ)      // 4096
#define N_QKV   (3*EMB)          // 6144
#define KP      2048             // plain fp16 GEMM K

// ======================= scratch (device globals) ================
__device__ __half g_qkvh[(size_t)BT * N_QKV];          // qkv fp16
__device__ __half g_qh[(size_t)BATCH*NHEAD*SEQ*HDIM];  // [b,h,t,d] (scaled)
__device__ __half g_kh[(size_t)BATCH*NHEAD*SEQ*HDIM];  // [b,h,t,d]
__device__ __half g_vt[(size_t)BATCH*NHEAD*HDIM*SEQ];  // [b,h,d,t] transposed
__device__ __half g_Ax  [(size_t)BT * KP];             // x fp16
__device__ __half g_Aao [(size_t)BT * KP];             // attn-out fp16
__device__ __half g_Bqkv[(size_t)N_QKV * KP];          // Wqkv^T fp16
__device__ __half g_Bout[(size_t)EMB * KP];            // Wout^T fp16
__device__ float  g_rope[(size_t)SEQ * 32];            // [t][0:16)=cos, [t][16:32)=sin

// ======================= helpers =================================
__device__ __forceinline__ u32 smem_u32(const void* p){
    u32 a; asm("{ .reg .u64 t; cvta.to.shared.u64 t, %1; cvt.u32.u64 %0, t; }" : "=r"(a) : "l"(p));
    return a;
}
#define SWZ128(off) ((off) ^ (((off) >> 3) & 0x70))

__device__ __forceinline__ void cpasync16(u32 daddr, const void* gptr){
    asm volatile("cp.async.cg.shared.global [%0], [%1], 16;" :: "r"(daddr), "l"(gptr));
}
#define CP_COMMIT() asm volatile("cp.async.commit_group;")
#define CP_WAIT(n)  asm volatile("cp.async.wait_group %0;" :: "n"(n))

__device__ __forceinline__ void ldsm4(u32* r, u32 addr){
    asm volatile("ldmatrix.sync.aligned.m8n8.x4.shared.b16 {%0,%1,%2,%3}, [%4];"
        : "=r"(r[0]), "=r"(r[1]), "=r"(r[2]), "=r"(r[3]) : "r"(addr));
}
__device__ __forceinline__ void mma16816h(float* c, const u32* a, u32 b0, u32 b1){
    asm volatile("mma.sync.aligned.m16n8k16.row.col.f32.f16.f16.f32 "
        "{%0,%1,%2,%3}, {%4,%5,%6,%7}, {%8,%9}, {%0,%1,%2,%3};"
        : "+f"(c[0]), "+f"(c[1]), "+f"(c[2]), "+f"(c[3])
        : "r"(a[0]), "r"(a[1]), "r"(a[2]), "r"(a[3]), "r"(b0), "r"(b1));
}
// pack two fp32 -> f16x2 register: lo half = a, hi half = b
__device__ __forceinline__ u32 h2pack(float a, float b){
    u32 r;
    asm("cvt.rn.f16x2.f32 %0, %2, %1;" : "=r"(r) : "f"(a), "f"(b));
    return r;
}

// =============================================================================
// Setup: RoPE cos/sin table  [t][i] for i<16
// =============================================================================
__global__ void rope_table(float* __restrict__ T)
{
    const int idx = blockIdx.x*blockDim.x + threadIdx.x;   // 0..32767
    if (idx >= SEQ*16) return;
    const int t = idx >> 4, i = idx & 15;
    const float invf = expf(-(float)i * (9.210340371976184f / 16.0f));
    float sn, cs; sincosf((float)t * invf, &sn, &cs);
    T[t*32 + i]      = cs;
    T[t*32 + 16 + i] = sn;
}

// =============================================================================
// Conversions
// =============================================================================
// rows [R, 2048] fp32 -> fp16
__global__ void conv_rows(const float* __restrict__ X, __half* __restrict__ Ap, int R)
{
    size_t idx = (size_t)blockIdx.x*blockDim.x + threadIdx.x;
    if (idx >= (size_t)R*512) return;
    float4 x = *(const float4*)(X + idx*4);
    __half h[4] = { __float2half_rn(x.x), __float2half_rn(x.y),
                    __float2half_rn(x.z), __float2half_rn(x.w) };
    *(ull*)(Ap + idx*4) = *(const ull*)h;
}

// W [2048, N] fp32 -> Bp [N, 2048] fp16 (transpose)
__global__ void conv_BT(const float* __restrict__ W, __half* __restrict__ Bp, int N)
{
    __shared__ float tile[32][33];
    const int n0 = blockIdx.x*32, k0 = blockIdx.y*32;
    const int tx = threadIdx.x, ty = threadIdx.y;
    #pragma unroll
    for (int j=0;j<4;j++)
        tile[ty*4+j][tx] = W[(size_t)(k0+ty*4+j)*N + n0 + tx];
    __syncthreads();
    #pragma unroll
    for (int j=0;j<4;j++)
        Bp[(size_t)(n0+ty*4+j)*KP + k0 + tx] = __float2half_rn(tile[tx][ty*4+j]);
}

// =============================================================================
// HMMA GEMM (fp16, K=2048): C[M,N] = A[M,KP] * B[N,KP]^T + bias
// 128x256 CTA, 16 warps 4x4, warp 32x64, 3-stage cp.async ring, GK=64.
// Output type templated: fp32 (final) or fp16 (qkv intermediate).
// =============================================================================
#define GK 64
#define NC (KP/GK)              // 32
#define STAGE_A 16384
#define STAGE_B 32768
#define STAGE   (STAGE_A + STAGE_B)
#define NSTG 3
#define GEMM_SMEM (NSTG*STAGE)

template<typename OT>
__global__ __launch_bounds__(512, 1)
void gemm_hmma(const __half* __restrict__ A,
               const __half* __restrict__ B,
               const float* __restrict__ bias,
               OT* __restrict__ C, int N)
{
    extern __shared__ char smem[];
    const u32 sb = smem_u32(smem);
    const int tid  = threadIdx.x;
    const int wid  = tid >> 5;
    const int lane = tid & 31;
    const int wm = wid & 3;
    const int wn = wid >> 2;
    const int m0 = blockIdx.y * 128;
    const int n0 = blockIdx.x * 256;

    const __half* Ab = A + (size_t)m0 * KP;
    const __half* Bb = B + (size_t)n0 * KP;

    const int alr = tid >> 2;
    const int alk = (tid & 3) * 2;
    const int blr = tid >> 1;
    const int blk = (tid & 1) * 4;
    auto load_stage = [&](int kc, u32 off){
        const __half* Ag = Ab + (size_t)alr*KP + kc*GK + alk*8;
        #pragma unroll
        for (int j=0;j<2;j++)
            cpasync16(sb + off + SWZ128(alr*128 + (alk+j)*16), Ag + j*8);
        const __half* Bg = Bb + (size_t)blr*KP + kc*GK + blk*8;
        #pragma unroll
        for (int j=0;j<4;j++)
            cpasync16(sb + off + STAGE_A + SWZ128(blr*128 + (blk+j)*16), Bg + j*8);
    };

    float acc[2][8][4];
    #pragma unroll
    for (int a=0;a<2;a++)
        #pragma unroll
        for (int b=0;b<8;b++)
            #pragma unroll
            for (int c=0;c<4;c++) acc[a][b][c] = 0.f;

    load_stage(0, 0);       CP_COMMIT();
    load_stage(1, STAGE);   CP_COMMIT();

    const int arow = wm*32 + (lane & 15);
    const int akof = (lane >> 4) * 8;
    const int brow = wn*64 + ((lane >> 4) & 1)*8 + (lane & 7);
    const int bkof = ((lane >> 3) & 1) * 8;

    int slot = 0;
    for (int i=0; i<NC; i++){
        CP_WAIT(1);
        __syncthreads();

        if (i+2 < NC){
            int ns = slot + 2; if (ns >= NSTG) ns -= NSTG;
            load_stage(i+2, (u32)ns * STAGE);
        }
        CP_COMMIT();

        const u32 abase = sb + (u32)slot * STAGE;
        const u32 bbase = abase + STAGE_A;

        #pragma unroll
        for (int ks=0; ks<4; ks++){
            const int k0 = ks*16;
            u32 afr[2][4];
            #pragma unroll
            for (int mf=0; mf<2; mf++)
                ldsm4(afr[mf], abase + SWZ128((arow + mf*16)*128 + (k0 + akof)*2));
            u32 bfr[4][4];
            #pragma unroll
            for (int nq=0; nq<4; nq++)
                ldsm4(bfr[nq], bbase + SWZ128((brow + nq*16)*128 + (k0 + bkof)*2));
            #pragma unroll
            for (int mf=0; mf<2; mf++)
                #pragma unroll
                for (int nq=0; nq<4; nq++){
                    mma16816h(acc[mf][nq*2+0], afr[mf], bfr[nq][0], bfr[nq][1]);
                    mma16816h(acc[mf][nq*2+1], afr[mf], bfr[nq][2], bfr[nq][3]);
                }
        }
        slot++; if (slot >= NSTG) slot = 0;
    }

    #pragma unroll
    for (int mf=0; mf<2; mf++){
        const int r = m0 + wm*32 + mf*16 + (lane >> 2);
        #pragma unroll
        for (int nf=0; nf<8; nf++){
            const int c = n0 + wn*64 + nf*8 + (lane & 3)*2;
            const float b0 = bias[c], b1 = bias[c+1];
            OT* cp = C + (size_t)r*N + c;
            if constexpr (sizeof(OT) == 2){
                *(u32*)cp = h2pack(acc[mf][nf][0] + b0, acc[mf][nf][1] + b1);
                *(u32*)(cp + 8*(size_t)N) = h2pack(acc[mf][nf][2] + b0, acc[mf][nf][3] + b1);
            } else {
                *(float2*)cp = make_float2(acc[mf][nf][0] + b0, acc[mf][nf][1] + b1);
                *(float2*)(cp + 8*(size_t)N) = make_float2(acc[mf][nf][2] + b0, acc[mf][nf][3] + b1);
            }
        }
    }
}

// =============================================================================
// RoPE + scatter, tile-transposing version. Block = (64-token tile, one (b,h)).
// All global reads/writes are 16B vectorized and fully coalesced; the v
// transpose goes through smem.
// =============================================================================
#define PADH 72
__global__ __launch_bounds__(256)
void rope_scatter(const __half* __restrict__ qkv,
                  const float* __restrict__ T,
                  __half* __restrict__ qh, __half* __restrict__ kh,
                  __half* __restrict__ vt)
{
    __shared__ __half s[3][64][PADH];
    const int tt = blockIdx.x;
    const int bh = blockIdx.y;
    const int b = bh >> 5, h = bh & 31;
    const int t0 = tt*64;
    const int tid = threadIdx.x;

    // ---- load q/k/v 64x64 tiles (coalesced 128B rows)
    #pragma unroll
    for (int seg=0; seg<3; seg++){
        #pragma unroll
        for (int p=0; p<2; p++){
            const int idx = tid + p*256;
            const int r = idx >> 3, c8 = (idx & 7)*8;
            const __half* g = qkv + ((size_t)(b*SEQ + t0 + r))*N_QKV + seg*EMB + h*64 + c8;
            *(uint4*)&s[seg][r][c8] = *(const uint4*)g;
        }
    }
    __syncthreads();

    // ---- q/k RoPE + coalesced [t][d] stores
    #pragma unroll
    for (int p=0; p<2; p++){
        const int r  = (tid >> 3) + p*32;
        const int d8 = (tid & 7)*8;
        const float* Tc = T + (size_t)(t0 + r)*32;
        __half outq[8], outk[8];
        #pragma unroll
        for (int j=0; j<8; j++){
            const int d = d8 + j;
            float qv = __half2float(s[0][r][d]);
            float kv = __half2float(s[1][r][d]);
            if (d < 16){
                const float cs = Tc[d], sn = Tc[16 + d];
                const float q2 = __half2float(s[0][r][d + 16]);
                const float k2 = __half2float(s[1][r][d + 16]);
                qv = qv*cs - q2*sn;
                kv = kv*cs - k2*sn;
            } else if (d < 32){
                const int i = d - 16;
                const float cs = Tc[i], sn = Tc[16 + i];
                const float q1 = __half2float(s[0][r][d - 16]);
                const float k1 = __half2float(s[1][r][d - 16]);
                qv = q1*sn + qv*cs;
                kv = k1*sn + kv*cs;
            }
            outq[j] = __float2half(qv * 0.125f);
            outk[j] = __float2half(kv);
        }
        const size_t dst = ((size_t)bh*SEQ + t0 + r)*HDIM + d8;
        *(uint4*)(qh + dst) = *(uint4*)outq;
        *(uint4*)(kh + dst) = *(uint4*)outk;
    }

    // ---- v transpose + coalesced [d][t] stores
    #pragma unroll
    for (int p=0; p<2; p++){
        const int d  = (tid >> 3) + p*32;
        const int t8 = (tid & 7)*8;
        __half outv[8];
        #pragma unroll
        for (int j=0; j<8; j++) outv[j] = s[2][t8 + j][d];
        *(uint4*)(vt + ((size_t)bh*HDIM + d)*SEQ + t0 + t8) = *(uint4*)outv;
    }
}

// =============================================================================
// Flash attention, fp16 HMMA, causal. Epilogue writes fp16 Aao [BT, 2048].
// =============================================================================
#define FA_KV   16384
#define FA_SMEM (16384 + 3*FA_KV)        // 64 KB

__global__ __launch_bounds__(256, 2)
void flash_hmma(const __half* __restrict__ Qh, const __half* __restrict__ Kh,
                const __half* __restrict__ Vt, __half* __restrict__ Aao)
{
    extern __shared__ char smem[];
    const u32 sb = smem_u32(smem);
    const int tid = threadIdx.x, wid = tid >> 5, lane = tid & 31;
    const int qt = (int)gridDim.x - 1 - (int)blockIdx.x;   // heavy tiles first
    const int bh = blockIdx.y;
    const size_t base = (size_t)bh * SEQ * HDIM;
    const int nkt = 2*qt + 2;

    {
        const int r = tid >> 1;
        const int g = (tid & 1) * 4;
        const __half* Qg = Qh + base + (size_t)(qt*128 + r)*HDIM + g*8;
        #pragma unroll
        for (int j=0;j<4;j++)
            cpasync16(sb + SWZ128(r*128 + (g+j)*16), Qg + j*8);
    }
    const int kvr = tid >> 2;
    const int kvg = (tid & 3) * 2;
    auto load_kv = [&](int kt, u32 off){
        const __half* Kg = Kh + base + (size_t)(kt*64 + kvr)*HDIM + kvg*8;
        cpasync16(sb + off        + SWZ128(kvr*128 +  kvg   *16), Kg);
        cpasync16(sb + off        + SWZ128(kvr*128 + (kvg+1)*16), Kg + 8);
        const __half* Vg = Vt + base + (size_t)kvr*SEQ + kt*64 + kvg*8;
        cpasync16(sb + off + 8192 + SWZ128(kvr*128 +  kvg   *16), Vg);
        cpasync16(sb + off + 8192 + SWZ128(kvr*128 + (kvg+1)*16), Vg + 8);
    };

    load_kv(0, 16384);              CP_COMMIT();
    if (nkt > 1) load_kv(1, 16384 + FA_KV);
    CP_COMMIT();

    CP_WAIT(1);
    __syncthreads();

    u32 aq[4][4];
    {
        const int arow = wid*16 + (lane & 15);
        const int akof = (lane >> 4) * 8;
        #pragma unroll
        for (int ks=0; ks<4; ks++)
            ldsm4(aq[ks], sb + SWZ128(arow*128 + (ks*16 + akof)*2));
    }

    const int brow = ((lane >> 4) & 1)*8 + (lane & 7);
    const int bkof = ((lane >> 3) & 1) * 8;
    const int rq   = qt*128 + wid*16 + (lane >> 2);

    float oacc[8][4];
    #pragma unroll
    for (int j=0;j<8;j++){ oacc[j][0]=0.f; oacc[j][1]=0.f; oacc[j][2]=0.f; oacc[j][3]=0.f; }
    float m0 = -1e30f, m1 = -1e30f, l0 = 0.f, l1 = 0.f;

    int slot = 0;
    for (int kt = 0; kt < nkt; kt++){
        if (kt > 0){ CP_WAIT(1); __syncthreads(); }
        if (kt+2 < nkt){
            int ns = slot + 2; if (ns >= 3) ns -= 3;
            load_kv(kt+2, 16384 + (u32)ns*FA_KV);
        }
        CP_COMMIT();

        const u32 kbase = sb + 16384 + (u32)slot*FA_KV;
        const u32 vbase = kbase + 8192;

        float sacc[8][4];
        #pragma unroll
        for (int j=0;j<8;j++){ sacc[j][0]=0.f; sacc[j][1]=0.f; sacc[j][2]=0.f; sacc[j][3]=0.f; }
        #pragma unroll
        for (int ks=0; ks<4; ks++){
            #pragma unroll
            for (int nq=0; nq<4; nq++){
                u32 bfr[4];
                ldsm4(bfr, kbase + SWZ128((nq*16 + brow)*128 + (ks*16 + bkof)*2));
                mma16816h(sacc[nq*2+0], aq[ks], bfr[0], bfr[1]);
                mma16816h(sacc[nq*2+1], aq[ks], bfr[2], bfr[3]);
            }
        }

        if (kt >= 2*qt){
            #pragma unroll
            for (int j=0;j<8;j++){
                const int c = kt*64 + (j>>1)*16 + ((j&1)<<3) + ((lane&3)<<1);
                if (c   > rq)   sacc[j][0] = -1e30f;
                if (c+1 > rq)   sacc[j][1] = -1e30f;
                if (c   > rq+8) sacc[j][2] = -1e30f;
                if (c+1 > rq+8) sacc[j][3] = -1e30f;
            }
        }

        float mx0 = -1e30f, mx1 = -1e30f;
        #pragma unroll
        for (int j=0;j<8;j++){
            mx0 = fmaxf(mx0, fmaxf(sacc[j][0], sacc[j][1]));
            mx1 = fmaxf(mx1, fmaxf(sacc[j][2], sacc[j][3]));
        }
        mx0 = fmaxf(mx0, __shfl_xor_sync(0xffffffffu, mx0, 1));
        mx0 = fmaxf(mx0, __shfl_xor_sync(0xffffffffu, mx0, 2));
        mx1 = fmaxf(mx1, __shfl_xor_sync(0xffffffffu, mx1, 1));
        mx1 = fmaxf(mx1, __shfl_xor_sync(0xffffffffu, mx1, 2));
        const float mn0 = fmaxf(m0, mx0), mn1 = fmaxf(m1, mx1);
        const float cr0 = __expf(m0 - mn0), cr1 = __expf(m1 - mn1);
        m0 = mn0; m1 = mn1;
        float rs0 = 0.f, rs1 = 0.f;
        #pragma unroll
        for (int j=0;j<8;j++){
            sacc[j][0] = __expf(sacc[j][0] - mn0); rs0 += sacc[j][0];
            sacc[j][1] = __expf(sacc[j][1] - mn0); rs0 += sacc[j][1];
            sacc[j][2] = __expf(sacc[j][2] - mn1); rs1 += sacc[j][2];
            sacc[j][3] = __expf(sacc[j][3] - mn1); rs1 += sacc[j][3];
        }
        rs0 += __shfl_xor_sync(0xffffffffu, rs0, 1);
        rs0 += __shfl_xor_sync(0xffffffffu, rs0, 2);
        rs1 += __shfl_xor_sync(0xffffffffu, rs1, 1);
        rs1 += __shfl_xor_sync(0xffffffffu, rs1, 2);
        l0 = l0*cr0 + rs0;
        l1 = l1*cr1 + rs1;
        #pragma unroll
        for (int j=0;j<8;j++){
            oacc[j][0] *= cr0; oacc[j][1] *= cr0;
            oacc[j][2] *= cr1; oacc[j][3] *= cr1;
        }

        #pragma unroll
        for (int kc=0; kc<4; kc++){
            u32 ap[4];
            ap[0] = h2pack(sacc[2*kc  ][0], sacc[2*kc  ][1]);
            ap[1] = h2pack(sacc[2*kc  ][2], sacc[2*kc  ][3]);
            ap[2] = h2pack(sacc[2*kc+1][0], sacc[2*kc+1][1]);
            ap[3] = h2pack(sacc[2*kc+1][2], sacc[2*kc+1][3]);
            #pragma unroll
            for (int nq=0; nq<4; nq++){
                u32 bfr[4];
                ldsm4(bfr, vbase + SWZ128((nq*16 + brow)*128 + (kc*16 + bkof)*2));
                mma16816h(oacc[nq*2+0], ap, bfr[0], bfr[1]);
                mma16816h(oacc[nq*2+1], ap, bfr[2], bfr[3]);
            }
        }
        slot++; if (slot >= 3) slot = 0;
    }

    // ---- epilogue: normalize, write fp16 Aao [b*SEQ+t][2048]
    const float inv0 = 1.f / l0, inv1 = 1.f / l1;
    const int b = bh >> 5, h = bh & 31;
    const int t0 = qt*128 + wid*16 + (lane >> 2);
    __half* a0 = Aao + ((size_t)(b*SEQ + t0))*EMB + h*64;
    __half* a1 = a0 + 8*(size_t)EMB;
    #pragma unroll
    for (int j=0;j<8;j++){
        const int c = (j>>1)*16 + ((j&1)<<3) + ((lane&3)<<1);
        *(u32*)(a0 + c) = h2pack(oacc[j][0]*inv0, oacc[j][1]*inv0);
        *(u32*)(a1 + c) = h2pack(oacc[j][2]*inv1, oacc[j][3]*inv1);
    }
}

// =============================================================================
extern "C" void kernel_launch(void* const* d_in, const int* in_sizes, int n_in,
                              void* d_out, int out_size)
{
    (void)in_sizes; (void)n_in; (void)out_size;
    const float* x    = (const float*)d_in[0];
    const float* Wqkv = (const float*)d_in[1];
    const float* bqkv = (const float*)d_in[2];
    const float* Wout = (const float*)d_in[3];
    const float* bout = (const float*)d_in[4];
    float* out = (float*)d_out;

    __half *qkvh, *qh, *kh, *vt, *Ax, *Aao, *Bqkv, *Bout;
    float* rope;
    cudaGetSymbolAddress((void**)&qkvh, g_qkvh);
    cudaGetSymbolAddress((void**)&qh,  g_qh);
    cudaGetSymbolAddress((void**)&kh,  g_kh);
    cudaGetSymbolAddress((void**)&vt,  g_vt);
    cudaGetSymbolAddress((void**)&Ax,   g_Ax);
    cudaGetSymbolAddress((void**)&Aao,  g_Aao);
    cudaGetSymbolAddress((void**)&Bqkv, g_Bqkv);
    cudaGetSymbolAddress((void**)&Bout, g_Bout);
    cudaGetSymbolAddress((void**)&rope, g_rope);

    cudaFuncSetAttribute(gemm_hmma<__half>, cudaFuncAttributeMaxDynamicSharedMemorySize, GEMM_SMEM);
    cudaFuncSetAttribute(gemm_hmma<float>,  cudaFuncAttributeMaxDynamicSharedMemorySize, GEMM_SMEM);
    cudaFuncSetAttribute(flash_hmma, cudaFuncAttributeMaxDynamicSharedMemorySize, FA_SMEM);

    // 0) setup + fp16 conversions
    rope_table<<<(SEQ*16 + 255)/256, 256>>>(rope);
    conv_rows<<<(BT*512 + 255)/256, 256>>>(x, Ax, BT);
    conv_BT<<<dim3(N_QKV/32, EMB/32), dim3(32,8)>>>(Wqkv, Bqkv, N_QKV);
    conv_BT<<<dim3(EMB/32,  EMB/32), dim3(32,8)>>>(Wout, Bout, EMB);

    // 1) QKV projection (fp16 HMMA, fp16 output)
    gemm_hmma<__half><<<dim3(N_QKV/256, BT/128), 512, GEMM_SMEM>>>(Ax, Bqkv, bqkv, qkvh, N_QKV);

    // 2) RoPE (table) + tile-transposing scatter (all IO coalesced)
    rope_scatter<<<dim3(SEQ/64, BATCH*NHEAD), 256>>>(qkvh, rope, qh, kh, vt);

    // 3) causal flash attention (fp16 tensor cores); writes fp16 Aao
    flash_hmma<<<dim3(SEQ/128, BATCH*NHEAD), 256, FA_SMEM>>>(qh, kh, vt, Aao);

    // 4) output projection (fp16 HMMA, fp32 output)
    gemm_hmma<float><<<dim3(EMB/256, BT/128), 512, GEMM_SMEM>>>(Aao, Bout, bout, out, EMB);
}

// round 14
// speedup vs baseline: 1.1034x; 1.0593x over previous
#include <cuda_runtime.h>
#include <cuda_fp16.h>
#include <cstdint>
#include <math.h>

typedef unsigned long long ull;
typedef unsigned int u32;

// ======================= problem constants =======================
#define BATCH   2
#define SEQ     2048
#define EMB     2048
#define NHEAD   32
#define HDIM    64
#define BT      (BATCH*SEQ)      // 4096
#define N_QKV   (3*EMB)          // 6144
#define KP      2048             // plain fp16 GEMM K

// ======================= scratch (device globals) ================
__device__ __half g_qh[(size_t)BATCH*NHEAD*SEQ*HDIM];  // [b,h,t,d] (rope, scaled)
__device__ __half g_kh[(size_t)BATCH*NHEAD*SEQ*HDIM];  // [b,h,t,d] (rope)
__device__ __half g_vh[(size_t)BATCH*NHEAD*SEQ*HDIM];  // [b,h,t,d]
__device__ __half g_Ax  [(size_t)BT * KP];             // x fp16
__device__ __half g_Aao [(size_t)BT * KP];             // attn-out fp16
__device__ __half g_Bqkv[(size_t)N_QKV * KP];          // Wqkv^T fp16
__device__ __half g_Bout[(size_t)EMB * KP];            // Wout^T fp16
__device__ float  g_rope[(size_t)SEQ * 32];            // [t][0:16)=cos, [t][16:32)=sin

// ======================= helpers =================================
__device__ __forceinline__ u32 smem_u32(const void* p){
    u32 a; asm("{ .reg .u64 t; cvta.to.shared.u64 t, %1; cvt.u32.u64 %0, t; }" : "=r"(a) : "l"(p));
    return a;
}
#define SWZ128(off) ((off) ^ (((off) >> 3) & 0x70))

__device__ __forceinline__ void cpasync16(u32 daddr, const void* gptr){
    asm volatile("cp.async.cg.shared.global [%0], [%1], 16;" :: "r"(daddr), "l"(gptr));
}
#define CP_COMMIT() asm volatile("cp.async.commit_group;")
#define CP_WAIT(n)  asm volatile("cp.async.wait_group %0;" :: "n"(n))

__device__ __forceinline__ void ldsm4(u32* r, u32 addr){
    asm volatile("ldmatrix.sync.aligned.m8n8.x4.shared.b16 {%0,%1,%2,%3}, [%4];"
        : "=r"(r[0]), "=r"(r[1]), "=r"(r[2]), "=r"(r[3]) : "r"(addr));
}
__device__ __forceinline__ void ldsm4t(u32* r, u32 addr){
    asm volatile("ldmatrix.sync.aligned.m8n8.x4.trans.shared.b16 {%0,%1,%2,%3}, [%4];"
        : "=r"(r[0]), "=r"(r[1]), "=r"(r[2]), "=r"(r[3]) : "r"(addr));
}
__device__ __forceinline__ void mma16816h(float* c, const u32* a, u32 b0, u32 b1){
    asm volatile("mma.sync.aligned.m16n8k16.row.col.f32.f16.f16.f32 "
        "{%0,%1,%2,%3}, {%4,%5,%6,%7}, {%8,%9}, {%0,%1,%2,%3};"
        : "+f"(c[0]), "+f"(c[1]), "+f"(c[2]), "+f"(c[3])
        : "r"(a[0]), "r"(a[1]), "r"(a[2]), "r"(a[3]), "r"(b0), "r"(b1));
}
// pack two fp32 -> f16x2 register: lo half = a, hi half = b
__device__ __forceinline__ u32 h2pack(float a, float b){
    u32 r;
    asm("cvt.rn.f16x2.f32 %0, %2, %1;" : "=r"(r) : "f"(a), "f"(b));
    return r;
}

// =============================================================================
// Setup: RoPE cos/sin table  [t][i] for i<16
// =============================================================================
__global__ void rope_table(float* __restrict__ T)
{
    const int idx = blockIdx.x*blockDim.x + threadIdx.x;
    if (idx >= SEQ*16) return;
    const int t = idx >> 4, i = idx & 15;
    const float invf = expf(-(float)i * (9.210340371976184f / 16.0f));
    float sn, cs; sincosf((float)t * invf, &sn, &cs);
    T[t*32 + i]      = cs;
    T[t*32 + 16 + i] = sn;
}

// =============================================================================
// Conversions
// =============================================================================
__global__ void conv_rows(const float* __restrict__ X, __half* __restrict__ Ap, int R)
{
    size_t idx = (size_t)blockIdx.x*blockDim.x + threadIdx.x;
    if (idx >= (size_t)R*512) return;
    float4 x = *(const float4*)(X + idx*4);
    __half h[4] = { __float2half_rn(x.x), __float2half_rn(x.y),
                    __float2half_rn(x.z), __float2half_rn(x.w) };
    *(ull*)(Ap + idx*4) = *(const ull*)h;
}

__global__ void conv_BT(const float* __restrict__ W, __half* __restrict__ Bp, int N)
{
    __shared__ float tile[32][33];
    const int n0 = blockIdx.x*32, k0 = blockIdx.y*32;
    const int tx = threadIdx.x, ty = threadIdx.y;
    #pragma unroll
    for (int j=0;j<4;j++)
        tile[ty*4+j][tx] = W[(size_t)(k0+ty*4+j)*N + n0 + tx];
    __syncthreads();
    #pragma unroll
    for (int j=0;j<4;j++)
        Bp[(size_t)(n0+ty*4+j)*KP + k0 + tx] = __float2half_rn(tile[tx][ty*4+j]);
}

// =============================================================================
// Shared GEMM mainloop config
// =============================================================================
#define GK 64
#define NC (KP/GK)              // 32
#define STAGE_A 16384
#define STAGE_B 32768
#define STAGE   (STAGE_A + STAGE_B)
#define NSTG 3
#define GEMM_SMEM (NSTG*STAGE)

// mainloop macro body shared by both GEMMs (identical round-11 structure)
#define GEMM_MAINLOOP(Aptr, Bptr)                                              \
    const __half* Ab = (Aptr) + (size_t)m0 * KP;                               \
    const __half* Bb = (Bptr) + (size_t)n0 * KP;                               \
    const int alr = tid >> 2;                                                  \
    const int alk = (tid & 3) * 2;                                             \
    const int blr = tid >> 1;                                                  \
    const int blk = (tid & 1) * 4;                                             \
    auto load_stage = [&](int kc, u32 off){                                    \
        const __half* Ag = Ab + (size_t)alr*KP + kc*GK + alk*8;                \
        _Pragma("unroll")                                                      \
        for (int j=0;j<2;j++)                                                  \
            cpasync16(sb + off + SWZ128(alr*128 + (alk+j)*16), Ag + j*8);      \
        const __half* Bg = Bb + (size_t)blr*KP + kc*GK + blk*8;                \
        _Pragma("unroll")                                                      \
        for (int j=0;j<4;j++)                                                  \
            cpasync16(sb + off + STAGE_A + SWZ128(blr*128 + (blk+j)*16), Bg + j*8); \
    };                                                                         \
    float acc[2][8][4];                                                        \
    _Pragma("unroll")                                                          \
    for (int a=0;a<2;a++)                                                      \
        _Pragma("unroll")                                                      \
        for (int b2=0;b2<8;b2++)                                               \
            _Pragma("unroll")                                                  \
            for (int c=0;c<4;c++) acc[a][b2][c] = 0.f;                         \
    load_stage(0, 0);       CP_COMMIT();                                       \
    load_stage(1, STAGE);   CP_COMMIT();                                       \
    const int arow = wm*32 + (lane & 15);                                      \
    const int akof = (lane >> 4) * 8;                                          \
    const int brow = wn*64 + ((lane >> 4) & 1)*8 + (lane & 7);                 \
    const int bkof = ((lane >> 3) & 1) * 8;                                    \
    int slot = 0;                                                              \
    for (int i=0; i<NC; i++){                                                  \
        CP_WAIT(1);                                                            \
        __syncthreads();                                                       \
        if (i+2 < NC){                                                         \
            int ns = slot + 2; if (ns >= NSTG) ns -= NSTG;                     \
            load_stage(i+2, (u32)ns * STAGE);                                  \
        }                                                                      \
        CP_COMMIT();                                                           \
        const u32 abase = sb + (u32)slot * STAGE;                              \
        const u32 bbase = abase + STAGE_A;                                     \
        _Pragma("unroll")                                                      \
        for (int ks=0; ks<4; ks++){                                            \
            const int k0 = ks*16;                                              \
            u32 afr[2][4];                                                     \
            _Pragma("unroll")                                                  \
            for (int mf=0; mf<2; mf++)                                         \
                ldsm4(afr[mf], abase + SWZ128((arow + mf*16)*128 + (k0 + akof)*2)); \
            u32 bfr[4][4];                                                     \
            _Pragma("unroll")                                                  \
            for (int nq=0; nq<4; nq++)                                         \
                ldsm4(bfr[nq], bbase + SWZ128((brow + nq*16)*128 + (k0 + bkof)*2)); \
            _Pragma("unroll")                                                  \
            for (int mf=0; mf<2; mf++)                                         \
                _Pragma("unroll")                                              \
                for (int nq=0; nq<4; nq++){                                    \
                    mma16816h(acc[mf][nq*2+0], afr[mf], bfr[nq][0], bfr[nq][1]); \
                    mma16816h(acc[mf][nq*2+1], afr[mf], bfr[nq][2], bfr[nq][3]); \
                }                                                              \
        }                                                                      \
        slot++; if (slot >= NSTG) slot = 0;                                    \
    }

// =============================================================================
// QKV GEMM with fused bias + RoPE + scatter to qh/kh/vh [b,h,t,d] fp16.
// Each warp's 64-col tile is one head of one segment; rope partner d±16 is
// acc[mf][nf±2] in the same thread.
// =============================================================================
__global__ __launch_bounds__(512, 1)
void gemm_qkv_rope(const __half* __restrict__ A,
                   const __half* __restrict__ B,
                   const float* __restrict__ bias,
                   const float* __restrict__ T,
                   __half* __restrict__ qh, __half* __restrict__ kh,
                   __half* __restrict__ vh)
{
    extern __shared__ char smem[];
    const u32 sb = smem_u32(smem);
    const int tid  = threadIdx.x;
    const int wid  = tid >> 5;
    const int lane = tid & 31;
    const int wm = wid & 3;
    const int wn = wid >> 2;
    const int m0 = blockIdx.y * 128;
    const int n0 = blockIdx.x * 256;

    GEMM_MAINLOOP(A, B)

    // ---- epilogue: bias + rope + scatter
    const int c0  = n0 + wn*64;          // 64-aligned: one head
    const int seg = c0 >> 11;            // 0=q, 1=k, 2=v
    const int h   = (c0 >> 6) & 31;
    const float scale = (seg == 0) ? 0.125f : 1.0f;
    __half* dstbase = (seg == 0) ? qh : (seg == 1) ? kh : vh;

    #pragma unroll
    for (int mf=0; mf<2; mf++){
        const int r = m0 + wm*32 + mf*16 + (lane >> 2);
        const int b = r >> 11, t = r & 2047;
        float vv[8][4];
        #pragma unroll
        for (int nf=0; nf<8; nf++){
            const int c = c0 + nf*8 + (lane & 3)*2;
            const float b0 = bias[c], b1 = bias[c+1];
            vv[nf][0] = acc[mf][nf][0] + b0;
            vv[nf][1] = acc[mf][nf][1] + b1;
            vv[nf][2] = acc[mf][nf][2] + b0;
            vv[nf][3] = acc[mf][nf][3] + b1;
        }
        if (seg < 2){
            #pragma unroll
            for (int nf=0; nf<2; nf++){
                #pragma unroll
                for (int q=0; q<4; q++){
                    const int i  = nf*8 + (lane & 3)*2 + (q & 1);
                    const int tt = t + (q >> 1)*8;
                    const float cs = T[tt*32 + i], sn = T[tt*32 + 16 + i];
                    const float x1 = vv[nf][q], x2 = vv[nf+2][q];
                    vv[nf][q]   = x1*cs - x2*sn;
                    vv[nf+2][q] = x1*sn + x2*cs;
                }
            }
        }
        __half* dst = dstbase + ((size_t)(b*NHEAD + h)*SEQ + t)*HDIM;
        #pragma unroll
        for (int nf=0; nf<8; nf++){
            const int d = nf*8 + (lane & 3)*2;
            *(u32*)(dst + d)            = h2pack(vv[nf][0]*scale, vv[nf][1]*scale);
            *(u32*)(dst + 8*HDIM + d)   = h2pack(vv[nf][2]*scale, vv[nf][3]*scale);
        }
    }
}

// =============================================================================
// Output-projection GEMM (fp32 out + bias), round-11 epilogue.
// =============================================================================
__global__ __launch_bounds__(512, 1)
void gemm_out(const __half* __restrict__ A,
              const __half* __restrict__ B,
              const float* __restrict__ bias,
              float* __restrict__ C, int N)
{
    extern __shared__ char smem[];
    const u32 sb = smem_u32(smem);
    const int tid  = threadIdx.x;
    const int wid  = tid >> 5;
    const int lane = tid & 31;
    const int wm = wid & 3;
    const int wn = wid >> 2;
    const int m0 = blockIdx.y * 128;
    const int n0 = blockIdx.x * 256;

    GEMM_MAINLOOP(A, B)

    #pragma unroll
    for (int mf=0; mf<2; mf++){
        const int r = m0 + wm*32 + mf*16 + (lane >> 2);
        #pragma unroll
        for (int nf=0; nf<8; nf++){
            const int c = n0 + wn*64 + nf*8 + (lane & 3)*2;
            const float b0 = bias[c], b1 = bias[c+1];
            float* cp = C + (size_t)r*N + c;
            *(float2*)cp = make_float2(acc[mf][nf][0] + b0, acc[mf][nf][1] + b1);
            *(float2*)(cp + 8*(size_t)N) = make_float2(acc[mf][nf][2] + b0, acc[mf][nf][3] + b1);
        }
    }
}

// =============================================================================
// Flash attention, fp16 HMMA, causal. V in [t][d] layout (same as K);
// PV B-operand via ldmatrix.trans. Epilogue writes fp16 Aao [BT, 2048].
// =============================================================================
#define FA_KV   16384
#define FA_SMEM (16384 + 3*FA_KV)        // 64 KB

__global__ __launch_bounds__(256, 2)
void flash_hmma(const __half* __restrict__ Qh, const __half* __restrict__ Kh,
                const __half* __restrict__ Vh, __half* __restrict__ Aao)
{
    extern __shared__ char smem[];
    const u32 sb = smem_u32(smem);
    const int tid = threadIdx.x, wid = tid >> 5, lane = tid & 31;
    const int qt = (int)gridDim.x - 1 - (int)blockIdx.x;   // heavy tiles first
    const int bh = blockIdx.y;
    const size_t base = (size_t)bh * SEQ * HDIM;
    const int nkt = 2*qt + 2;

    {
        const int r = tid >> 1;
        const int g = (tid & 1) * 4;
        const __half* Qg = Qh + base + (size_t)(qt*128 + r)*HDIM + g*8;
        #pragma unroll
        for (int j=0;j<4;j++)
            cpasync16(sb + SWZ128(r*128 + (g+j)*16), Qg + j*8);
    }
    const int kvr = tid >> 2;
    const int kvg = (tid & 3) * 2;
    auto load_kv = [&](int kt, u32 off){
        const __half* Kg = Kh + base + (size_t)(kt*64 + kvr)*HDIM + kvg*8;
        cpasync16(sb + off        + SWZ128(kvr*128 +  kvg   *16), Kg);
        cpasync16(sb + off        + SWZ128(kvr*128 + (kvg+1)*16), Kg + 8);
        const __half* Vg = Vh + base + (size_t)(kt*64 + kvr)*HDIM + kvg*8;
        cpasync16(sb + off + 8192 + SWZ128(kvr*128 +  kvg   *16), Vg);
        cpasync16(sb + off + 8192 + SWZ128(kvr*128 + (kvg+1)*16), Vg + 8);
    };

    load_kv(0, 16384);              CP_COMMIT();
    if (nkt > 1) load_kv(1, 16384 + FA_KV);
    CP_COMMIT();

    CP_WAIT(1);
    __syncthreads();

    u32 aq[4][4];
    {
        const int arow = wid*16 + (lane & 15);
        const int akof = (lane >> 4) * 8;
        #pragma unroll
        for (int ks=0; ks<4; ks++)
            ldsm4(aq[ks], sb + SWZ128(arow*128 + (ks*16 + akof)*2));
    }

    const int brow = ((lane >> 4) & 1)*8 + (lane & 7);
    const int bkof = ((lane >> 3) & 1) * 8;
    // trans-V lane mapping: k-row group from bit3, n-col group from bit4
    const int vrow = ((lane >> 3) & 1)*8 + (lane & 7);
    const int vnof = ((lane >> 4) & 1)*8;
    const int rq   = qt*128 + wid*16 + (lane >> 2);

    float oacc[8][4];
    #pragma unroll
    for (int j=0;j<8;j++){ oacc[j][0]=0.f; oacc[j][1]=0.f; oacc[j][2]=0.f; oacc[j][3]=0.f; }
    float m0 = -1e30f, m1 = -1e30f, l0 = 0.f, l1 = 0.f;

    int slot = 0;
    for (int kt = 0; kt < nkt; kt++){
        if (kt > 0){ CP_WAIT(1); __syncthreads(); }
        if (kt+2 < nkt){
            int ns = slot + 2; if (ns >= 3) ns -= 3;
            load_kv(kt+2, 16384 + (u32)ns*FA_KV);
        }
        CP_COMMIT();

        const u32 kbase = sb + 16384 + (u32)slot*FA_KV;
        const u32 vbase = kbase + 8192;

        float sacc[8][4];
        #pragma unroll
        for (int j=0;j<8;j++){ sacc[j][0]=0.f; sacc[j][1]=0.f; sacc[j][2]=0.f; sacc[j][3]=0.f; }
        #pragma unroll
        for (int ks=0; ks<4; ks++){
            #pragma unroll
            for (int nq=0; nq<4; nq++){
                u32 bfr[4];
                ldsm4(bfr, kbase + SWZ128((nq*16 + brow)*128 + (ks*16 + bkof)*2));
                mma16816h(sacc[nq*2+0], aq[ks], bfr[0], bfr[1]);
                mma16816h(sacc[nq*2+1], aq[ks], bfr[2], bfr[3]);
            }
        }

        if (kt >= 2*qt){
            #pragma unroll
            for (int j=0;j<8;j++){
                const int c = kt*64 + (j>>1)*16 + ((j&1)<<3) + ((lane&3)<<1);
                if (c   > rq)   sacc[j][0] = -1e30f;
                if (c+1 > rq)   sacc[j][1] = -1e30f;
                if (c   > rq+8) sacc[j][2] = -1e30f;
                if (c+1 > rq+8) sacc[j][3] = -1e30f;
            }
        }

        float mx0 = -1e30f, mx1 = -1e30f;
        #pragma unroll
        for (int j=0;j<8;j++){
            mx0 = fmaxf(mx0, fmaxf(sacc[j][0], sacc[j][1]));
            mx1 = fmaxf(mx1, fmaxf(sacc[j][2], sacc[j][3]));
        }
        mx0 = fmaxf(mx0, __shfl_xor_sync(0xffffffffu, mx0, 1));
        mx0 = fmaxf(mx0, __shfl_xor_sync(0xffffffffu, mx0, 2));
        mx1 = fmaxf(mx1, __shfl_xor_sync(0xffffffffu, mx1, 1));
        mx1 = fmaxf(mx1, __shfl_xor_sync(0xffffffffu, mx1, 2));
        const float mn0 = fmaxf(m0, mx0), mn1 = fmaxf(m1, mx1);
        const float cr0 = __expf(m0 - mn0), cr1 = __expf(m1 - mn1);
        m0 = mn0; m1 = mn1;
        float rs0 = 0.f, rs1 = 0.f;
        #pragma unroll
        for (int j=0;j<8;j++){
            sacc[j][0] = __expf(sacc[j][0] - mn0); rs0 += sacc[j][0];
            sacc[j][1] = __expf(sacc[j][1] - mn0); rs0 += sacc[j][1];
            sacc[j][2] = __expf(sacc[j][2] - mn1); rs1 += sacc[j][2];
            sacc[j][3] = __expf(sacc[j][3] - mn1); rs1 += sacc[j][3];
        }
        rs0 += __shfl_xor_sync(0xffffffffu, rs0, 1);
        rs0 += __shfl_xor_sync(0xffffffffu, rs0, 2);
        rs1 += __shfl_xor_sync(0xffffffffu, rs1, 1);
        rs1 += __shfl_xor_sync(0xffffffffu, rs1, 2);
        l0 = l0*cr0 + rs0;
        l1 = l1*cr1 + rs1;
        #pragma unroll
        for (int j=0;j<8;j++){
            oacc[j][0] *= cr0; oacc[j][1] *= cr0;
            oacc[j][2] *= cr1; oacc[j][3] *= cr1;
        }

        // O += P V  (V [t][d] via trans-ldmatrix)
        #pragma unroll
        for (int kc=0; kc<4; kc++){
            u32 ap[4];
            ap[0] = h2pack(sacc[2*kc  ][0], sacc[2*kc  ][1]);
            ap[1] = h2pack(sacc[2*kc  ][2], sacc[2*kc  ][3]);
            ap[2] = h2pack(sacc[2*kc+1][0], sacc[2*kc+1][1]);
            ap[3] = h2pack(sacc[2*kc+1][2], sacc[2*kc+1][3]);
            #pragma unroll
            for (int nq=0; nq<4; nq++){
                u32 bfr[4];
                ldsm4t(bfr, vbase + SWZ128((kc*16 + vrow)*128 + (nq*16 + vnof)*2));
                mma16816h(oacc[nq*2+0], ap, bfr[0], bfr[1]);
                mma16816h(oacc[nq*2+1], ap, bfr[2], bfr[3]);
            }
        }
        slot++; if (slot >= 3) slot = 0;
    }

    // ---- epilogue: normalize, write fp16 Aao [b*SEQ+t][2048]
    const float inv0 = 1.f / l0, inv1 = 1.f / l1;
    const int b = bh >> 5, h = bh & 31;
    const int t0 = qt*128 + wid*16 + (lane >> 2);
    __half* a0 = Aao + ((size_t)(b*SEQ + t0))*EMB + h*64;
    __half* a1 = a0 + 8*(size_t)EMB;
    #pragma unroll
    for (int j=0;j<8;j++){
        const int c = (j>>1)*16 + ((j&1)<<3) + ((lane&3)<<1);
        *(u32*)(a0 + c) = h2pack(oacc[j][0]*inv0, oacc[j][1]*inv0);
        *(u32*)(a1 + c) = h2pack(oacc[j][2]*inv1, oacc[j][3]*inv1);
    }
}

// =============================================================================
extern "C" void kernel_launch(void* const* d_in, const int* in_sizes, int n_in,
                              void* d_out, int out_size)
{
    (void)in_sizes; (void)n_in; (void)out_size;
    const float* x    = (const float*)d_in[0];
    const float* Wqkv = (const float*)d_in[1];
    const float* bqkv = (const float*)d_in[2];
    const float* Wout = (const float*)d_in[3];
    const float* bout = (const float*)d_in[4];
    float* out = (float*)d_out;

    __half *qh, *kh, *vh, *Ax, *Aao, *Bqkv, *Bout;
    float* rope;
    cudaGetSymbolAddress((void**)&qh,  g_qh);
    cudaGetSymbolAddress((void**)&kh,  g_kh);
    cudaGetSymbolAddress((void**)&vh,  g_vh);
    cudaGetSymbolAddress((void**)&Ax,   g_Ax);
    cudaGetSymbolAddress((void**)&Aao,  g_Aao);
    cudaGetSymbolAddress((void**)&Bqkv, g_Bqkv);
    cudaGetSymbolAddress((void**)&Bout, g_Bout);
    cudaGetSymbolAddress((void**)&rope, g_rope);

    cudaFuncSetAttribute(gemm_qkv_rope, cudaFuncAttributeMaxDynamicSharedMemorySize, GEMM_SMEM);
    cudaFuncSetAttribute(gemm_out,      cudaFuncAttributeMaxDynamicSharedMemorySize, GEMM_SMEM);
    cudaFuncSetAttribute(flash_hmma,    cudaFuncAttributeMaxDynamicSharedMemorySize, FA_SMEM);

    // 0) setup + fp16 conversions
    rope_table<<<(SEQ*16 + 255)/256, 256>>>(rope);
    conv_rows<<<(BT*512 + 255)/256, 256>>>(x, Ax, BT);
    conv_BT<<<dim3(N_QKV/32, EMB/32), dim3(32,8)>>>(Wqkv, Bqkv, N_QKV);
    conv_BT<<<dim3(EMB/32,  EMB/32), dim3(32,8)>>>(Wout, Bout, EMB);

    // 1) QKV projection with fused bias + RoPE + scatter
    gemm_qkv_rope<<<dim3(N_QKV/256, BT/128), 512, GEMM_SMEM>>>(Ax, Bqkv, bqkv, rope, qh, kh, vh);

    // 2) causal flash attention (fp16 tensor cores, trans-V); writes fp16 Aao
    flash_hmma<<<dim3(SEQ/128, BATCH*NHEAD), 256, FA_SMEM>>>(qh, kh, vh, Aao);

    // 3) output projection (fp16 HMMA, fp32 output)
    gemm_out<<<dim3(EMB/256, BT/128), 512, GEMM_SMEM>>>(Aao, Bout, bout, out, EMB);
}

// round 15
// speedup vs baseline: 1.1331x; 1.0269x over previous
#include <cuda_runtime.h>
#include <cuda_fp16.h>
#include <cstdint>
#include <math.h>

typedef unsigned long long ull;
typedef unsigned int u32;

// ======================= problem constants =======================
#define BATCH   2
#define SEQ     2048
#define EMB     2048
#define NHEAD   32
#define HDIM    64
#define BT      (BATCH*SEQ)      // 4096
#define N_QKV   (3*EMB)          // 6144
#define KP      2048             // plain fp16 GEMM K

// ======================= scratch (device globals) ================
__device__ __half g_qh[(size_t)BATCH*NHEAD*SEQ*HDIM];  // [b,h,t,d] (rope, scaled)
__device__ __half g_kh[(size_t)BATCH*NHEAD*SEQ*HDIM];  // [b,h,t,d] (rope)
__device__ __half g_vh[(size_t)BATCH*NHEAD*SEQ*HDIM];  // [b,h,t,d]
__device__ __half g_Ax  [(size_t)BT * KP];             // x fp16
__device__ __half g_Aao [(size_t)BT * KP];             // attn-out fp16
__device__ __half g_Bqkv[(size_t)N_QKV * KP];          // Wqkv^T fp16
__device__ __half g_Bout[(size_t)EMB * KP];            // Wout^T fp16
__device__ float  g_rope[(size_t)SEQ * 32];            // [t][0:16)=cos, [t][16:32)=sin

// ======================= helpers =================================
__device__ __forceinline__ u32 smem_u32(const void* p){
    u32 a; asm("{ .reg .u64 t; cvta.to.shared.u64 t, %1; cvt.u32.u64 %0, t; }" : "=r"(a) : "l"(p));
    return a;
}
#define SWZ128(off) ((off) ^ (((off) >> 3) & 0x70))

__device__ __forceinline__ void cpasync16(u32 daddr, const void* gptr){
    asm volatile("cp.async.cg.shared.global [%0], [%1], 16;" :: "r"(daddr), "l"(gptr));
}
#define CP_COMMIT() asm volatile("cp.async.commit_group;")
#define CP_WAIT(n)  asm volatile("cp.async.wait_group %0;" :: "n"(n))

__device__ __forceinline__ void ldsm4(u32* r, u32 addr){
    asm volatile("ldmatrix.sync.aligned.m8n8.x4.shared.b16 {%0,%1,%2,%3}, [%4];"
        : "=r"(r[0]), "=r"(r[1]), "=r"(r[2]), "=r"(r[3]) : "r"(addr));
}
__device__ __forceinline__ void ldsm4t(u32* r, u32 addr){
    asm volatile("ldmatrix.sync.aligned.m8n8.x4.trans.shared.b16 {%0,%1,%2,%3}, [%4];"
        : "=r"(r[0]), "=r"(r[1]), "=r"(r[2]), "=r"(r[3]) : "r"(addr));
}
__device__ __forceinline__ void mma16816h(float* c, const u32* a, u32 b0, u32 b1){
    asm volatile("mma.sync.aligned.m16n8k16.row.col.f32.f16.f16.f32 "
        "{%0,%1,%2,%3}, {%4,%5,%6,%7}, {%8,%9}, {%0,%1,%2,%3};"
        : "+f"(c[0]), "+f"(c[1]), "+f"(c[2]), "+f"(c[3])
        : "r"(a[0]), "r"(a[1]), "r"(a[2]), "r"(a[3]), "r"(b0), "r"(b1));
}
// pack two fp32 -> f16x2 register: lo half = a, hi half = b
__device__ __forceinline__ u32 h2pack(float a, float b){
    u32 r;
    asm("cvt.rn.f16x2.f32 %0, %2, %1;" : "=r"(r) : "f"(a), "f"(b));
    return r;
}

// =============================================================================
// Fused prep kernel: weight transposes (vectorized), x conversion, rope table.
// Grid partition:
//   [0, 3072)      Wqkv transpose tiles (96 n-tiles x 32 k-tiles)
//   [3072, 4096)   Wout transpose tiles (32 x 32)
//   [4096, 6144)   x fp32->fp16 (2048 blocks x 1024 float4)
//   [6144, 6272)   rope table
// =============================================================================
#define PREP_WQKV   3072
#define PREP_WOUT   4096
#define PREP_X      6144
#define PREP_TABLE  6272

__device__ __forceinline__ void convBT_tile(const float* __restrict__ W,
                                            __half* __restrict__ Bp,
                                            int N, int bid)
{
    __shared__ float tile[64][65];
    const int ntiles = N >> 6;
    const int k0 = (bid / ntiles) << 6;
    const int n0 = (bid % ntiles) << 6;
    const int tid = threadIdx.x;

    #pragma unroll
    for (int it=0; it<4; it++){
        const int slot = tid + it*256;
        const int r  = slot >> 4;          // k row 0..63
        const int c4 = (slot & 15) * 4;    // n col
        const float4 v = *(const float4*)(W + (size_t)(k0 + r)*N + n0 + c4);
        tile[r][c4+0] = v.x; tile[r][c4+1] = v.y;
        tile[r][c4+2] = v.z; tile[r][c4+3] = v.w;
    }
    __syncthreads();

    #pragma unroll
    for (int p=0; p<2; p++){
        const int task  = tid + p*256;
        const int chunk = task & 7;        // k 8-block
        const int rn    = task >> 3;       // n row 0..63
        __half h[8];
        #pragma unroll
        for (int j=0; j<8; j++)
            h[j] = __float2half_rn(tile[chunk*8 + j][rn]);
        *(uint4*)(Bp + (size_t)(n0 + rn)*KP + k0 + chunk*8) = *(const uint4*)h;
    }
}

__global__ __launch_bounds__(256)
void prep(const float* __restrict__ x, const float* __restrict__ Wqkv,
          const float* __restrict__ Wout,
          __half* __restrict__ Ax, __half* __restrict__ Bqkv,
          __half* __restrict__ Bout, float* __restrict__ T)
{
    const int bid = blockIdx.x;
    const int tid = threadIdx.x;
    if (bid < PREP_WQKV){
        convBT_tile(Wqkv, Bqkv, N_QKV, bid);
    } else if (bid < PREP_WOUT){
        convBT_tile(Wout, Bout, EMB, bid - PREP_WQKV);
    } else if (bid < PREP_X){
        const size_t base = (size_t)(bid - PREP_WOUT) * 4096;   // floats
        #pragma unroll
        for (int it=0; it<4; it++){
            const size_t i = base + (size_t)(tid + it*256) * 4;
            const float4 v = *(const float4*)(x + i);
            __half h[4] = { __float2half_rn(v.x), __float2half_rn(v.y),
                            __float2half_rn(v.z), __float2half_rn(v.w) };
            *(ull*)(Ax + i) = *(const ull*)h;
        }
    } else {
        const int idx = (bid - PREP_X)*256 + tid;
        if (idx < SEQ*16){
            const int t = idx >> 4, i = idx & 15;
            const float invf = expf(-(float)i * (9.210340371976184f / 16.0f));
            float sn, cs; sincosf((float)t * invf, &sn, &cs);
            T[t*32 + i]      = cs;
            T[t*32 + 16 + i] = sn;
        }
    }
}

// =============================================================================
// Shared GEMM mainloop config
// =============================================================================
#define GK 64
#define NC (KP/GK)              // 32
#define STAGE_A 16384
#define STAGE_B 32768
#define STAGE   (STAGE_A + STAGE_B)
#define NSTG 3
#define GEMM_SMEM (NSTG*STAGE)

#define GEMM_MAINLOOP(Aptr, Bptr)                                              \
    const __half* Ab = (Aptr) + (size_t)m0 * KP;                               \
    const __half* Bb = (Bptr) + (size_t)n0 * KP;                               \
    const int alr = tid >> 2;                                                  \
    const int alk = (tid & 3) * 2;                                             \
    const int blr = tid >> 1;                                                  \
    const int blk = (tid & 1) * 4;                                             \
    auto load_stage = [&](int kc, u32 off){                                    \
        const __half* Ag = Ab + (size_t)alr*KP + kc*GK + alk*8;                \
        _Pragma("unroll")                                                      \
        for (int j=0;j<2;j++)                                                  \
            cpasync16(sb + off + SWZ128(alr*128 + (alk+j)*16), Ag + j*8);      \
        const __half* Bg = Bb + (size_t)blr*KP + kc*GK + blk*8;                \
        _Pragma("unroll")                                                      \
        for (int j=0;j<4;j++)                                                  \
            cpasync16(sb + off + STAGE_A + SWZ128(blr*128 + (blk+j)*16), Bg + j*8); \
    };                                                                         \
    float acc[2][8][4];                                                        \
    _Pragma("unroll")                                                          \
    for (int a=0;a<2;a++)                                                      \
        _Pragma("unroll")                                                      \
        for (int b2=0;b2<8;b2++)                                               \
            _Pragma("unroll")                                                  \
            for (int c=0;c<4;c++) acc[a][b2][c] = 0.f;                         \
    load_stage(0, 0);       CP_COMMIT();                                       \
    load_stage(1, STAGE);   CP_COMMIT();                                       \
    const int arow = wm*32 + (lane & 15);                                      \
    const int akof = (lane >> 4) * 8;                                          \
    const int brow = wn*64 + ((lane >> 4) & 1)*8 + (lane & 7);                 \
    const int bkof = ((lane >> 3) & 1) * 8;                                    \
    int slot = 0;                                                              \
    for (int i=0; i<NC; i++){                                                  \
        CP_WAIT(1);                                                            \
        __syncthreads();                                                       \
        if (i+2 < NC){                                                         \
            int ns = slot + 2; if (ns >= NSTG) ns -= NSTG;                     \
            load_stage(i+2, (u32)ns * STAGE);                                  \
        }                                                                      \
        CP_COMMIT();                                                           \
        const u32 abase = sb + (u32)slot * STAGE;                              \
        const u32 bbase = abase + STAGE_A;                                     \
        _Pragma("unroll")                                                      \
        for (int ks=0; ks<4; ks++){                                            \
            const int k0 = ks*16;                                              \
            u32 afr[2][4];                                                     \
            _Pragma("unroll")                                                  \
            for (int mf=0; mf<2; mf++)                                         \
                ldsm4(afr[mf], abase + SWZ128((arow + mf*16)*128 + (k0 + akof)*2)); \
            u32 bfr[4][4];                                                     \
            _Pragma("unroll")                                                  \
            for (int nq=0; nq<4; nq++)                                         \
                ldsm4(bfr[nq], bbase + SWZ128((brow + nq*16)*128 + (k0 + bkof)*2)); \
            _Pragma("unroll")                                                  \
            for (int mf=0; mf<2; mf++)                                         \
                _Pragma("unroll")                                              \
                for (int nq=0; nq<4; nq++){                                    \
                    mma16816h(acc[mf][nq*2+0], afr[mf], bfr[nq][0], bfr[nq][1]); \
                    mma16816h(acc[mf][nq*2+1], afr[mf], bfr[nq][2], bfr[nq][3]); \
                }                                                              \
        }                                                                      \
        slot++; if (slot >= NSTG) slot = 0;                                    \
    }

// =============================================================================
// QKV GEMM with fused bias + RoPE + scatter to qh/kh/vh [b,h,t,d] fp16.
// =============================================================================
__global__ __launch_bounds__(512, 1)
void gemm_qkv_rope(const __half* __restrict__ A,
                   const __half* __restrict__ B,
                   const float* __restrict__ bias,
                   const float* __restrict__ T,
                   __half* __restrict__ qh, __half* __restrict__ kh,
                   __half* __restrict__ vh)
{
    extern __shared__ char smem[];
    const u32 sb = smem_u32(smem);
    const int tid  = threadIdx.x;
    const int wid  = tid >> 5;
    const int lane = tid & 31;
    const int wm = wid & 3;
    const int wn = wid >> 2;
    const int m0 = blockIdx.y * 128;
    const int n0 = blockIdx.x * 256;

    GEMM_MAINLOOP(A, B)

    // ---- epilogue: bias + rope + scatter
    const int c0  = n0 + wn*64;          // 64-aligned: one head
    const int seg = c0 >> 11;            // 0=q, 1=k, 2=v
    const int h   = (c0 >> 6) & 31;
    const float scale = (seg == 0) ? 0.125f : 1.0f;
    __half* dstbase = (seg == 0) ? qh : (seg == 1) ? kh : vh;

    #pragma unroll
    for (int mf=0; mf<2; mf++){
        const int r = m0 + wm*32 + mf*16 + (lane >> 2);
        const int b = r >> 11, t = r & 2047;
        float vv[8][4];
        #pragma unroll
        for (int nf=0; nf<8; nf++){
            const int c = c0 + nf*8 + (lane & 3)*2;
            const float b0 = bias[c], b1 = bias[c+1];
            vv[nf][0] = acc[mf][nf][0] + b0;
            vv[nf][1] = acc[mf][nf][1] + b1;
            vv[nf][2] = acc[mf][nf][2] + b0;
            vv[nf][3] = acc[mf][nf][3] + b1;
        }
        if (seg < 2){
            #pragma unroll
            for (int nf=0; nf<2; nf++){
                #pragma unroll
                for (int q=0; q<4; q++){
                    const int i  = nf*8 + (lane & 3)*2 + (q & 1);
                    const int tt = t + (q >> 1)*8;
                    const float cs = T[tt*32 + i], sn = T[tt*32 + 16 + i];
                    const float x1 = vv[nf][q], x2 = vv[nf+2][q];
                    vv[nf][q]   = x1*cs - x2*sn;
                    vv[nf+2][q] = x1*sn + x2*cs;
                }
            }
        }
        __half* dst = dstbase + ((size_t)(b*NHEAD + h)*SEQ + t)*HDIM;
        #pragma unroll
        for (int nf=0; nf<8; nf++){
            const int d = nf*8 + (lane & 3)*2;
            *(u32*)(dst + d)            = h2pack(vv[nf][0]*scale, vv[nf][1]*scale);
            *(u32*)(dst + 8*HDIM + d)   = h2pack(vv[nf][2]*scale, vv[nf][3]*scale);
        }
    }
}

// =============================================================================
// Output-projection GEMM (fp32 out + bias).
// =============================================================================
__global__ __launch_bounds__(512, 1)
void gemm_out(const __half* __restrict__ A,
              const __half* __restrict__ B,
              const float* __restrict__ bias,
              float* __restrict__ C, int N)
{
    extern __shared__ char smem[];
    const u32 sb = smem_u32(smem);
    const int tid  = threadIdx.x;
    const int wid  = tid >> 5;
    const int lane = tid & 31;
    const int wm = wid & 3;
    const int wn = wid >> 2;
    const int m0 = blockIdx.y * 128;
    const int n0 = blockIdx.x * 256;

    GEMM_MAINLOOP(A, B)

    #pragma unroll
    for (int mf=0; mf<2; mf++){
        const int r = m0 + wm*32 + mf*16 + (lane >> 2);
        #pragma unroll
        for (int nf=0; nf<8; nf++){
            const int c = n0 + wn*64 + nf*8 + (lane & 3)*2;
            const float b0 = bias[c], b1 = bias[c+1];
            float* cp = C + (size_t)r*N + c;
            *(float2*)cp = make_float2(acc[mf][nf][0] + b0, acc[mf][nf][1] + b1);
            *(float2*)(cp + 8*(size_t)N) = make_float2(acc[mf][nf][2] + b0, acc[mf][nf][3] + b1);
        }
    }
}

// =============================================================================
// Flash attention, fp16 HMMA, causal. V in [t][d] layout; PV via ldmatrix.trans.
// =============================================================================
#define FA_KV   16384
#define FA_SMEM (16384 + 3*FA_KV)        // 64 KB

__global__ __launch_bounds__(256, 2)
void flash_hmma(const __half* __restrict__ Qh, const __half* __restrict__ Kh,
                const __half* __restrict__ Vh, __half* __restrict__ Aao)
{
    extern __shared__ char smem[];
    const u32 sb = smem_u32(smem);
    const int tid = threadIdx.x, wid = tid >> 5, lane = tid & 31;
    const int qt = (int)gridDim.x - 1 - (int)blockIdx.x;   // heavy tiles first
    const int bh = blockIdx.y;
    const size_t base = (size_t)bh * SEQ * HDIM;
    const int nkt = 2*qt + 2;

    {
        const int r = tid >> 1;
        const int g = (tid & 1) * 4;
        const __half* Qg = Qh + base + (size_t)(qt*128 + r)*HDIM + g*8;
        #pragma unroll
        for (int j=0;j<4;j++)
            cpasync16(sb + SWZ128(r*128 + (g+j)*16), Qg + j*8);
    }
    const int kvr = tid >> 2;
    const int kvg = (tid & 3) * 2;
    auto load_kv = [&](int kt, u32 off){
        const __half* Kg = Kh + base + (size_t)(kt*64 + kvr)*HDIM + kvg*8;
        cpasync16(sb + off        + SWZ128(kvr*128 +  kvg   *16), Kg);
        cpasync16(sb + off        + SWZ128(kvr*128 + (kvg+1)*16), Kg + 8);
        const __half* Vg = Vh + base + (size_t)(kt*64 + kvr)*HDIM + kvg*8;
        cpasync16(sb + off + 8192 + SWZ128(kvr*128 +  kvg   *16), Vg);
        cpasync16(sb + off + 8192 + SWZ128(kvr*128 + (kvg+1)*16), Vg + 8);
    };

    load_kv(0, 16384);              CP_COMMIT();
    if (nkt > 1) load_kv(1, 16384 + FA_KV);
    CP_COMMIT();

    CP_WAIT(1);
    __syncthreads();

    u32 aq[4][4];
    {
        const int arow = wid*16 + (lane & 15);
        const int akof = (lane >> 4) * 8;
        #pragma unroll
        for (int ks=0; ks<4; ks++)
            ldsm4(aq[ks], sb + SWZ128(arow*128 + (ks*16 + akof)*2));
    }

    const int brow = ((lane >> 4) & 1)*8 + (lane & 7);
    const int bkof = ((lane >> 3) & 1) * 8;
    const int vrow = ((lane >> 3) & 1)*8 + (lane & 7);
    const int vnof = ((lane >> 4) & 1)*8;
    const int rq   = qt*128 + wid*16 + (lane >> 2);

    float oacc[8][4];
    #pragma unroll
    for (int j=0;j<8;j++){ oacc[j][0]=0.f; oacc[j][1]=0.f; oacc[j][2]=0.f; oacc[j][3]=0.f; }
    float m0 = -1e30f, m1 = -1e30f, l0 = 0.f, l1 = 0.f;

    int slot = 0;
    for (int kt = 0; kt < nkt; kt++){
        if (kt > 0){ CP_WAIT(1); __syncthreads(); }
        if (kt+2 < nkt){
            int ns = slot + 2; if (ns >= 3) ns -= 3;
            load_kv(kt+2, 16384 + (u32)ns*FA_KV);
        }
        CP_COMMIT();

        const u32 kbase = sb + 16384 + (u32)slot*FA_KV;
        const u32 vbase = kbase + 8192;

        float sacc[8][4];
        #pragma unroll
        for (int j=0;j<8;j++){ sacc[j][0]=0.f; sacc[j][1]=0.f; sacc[j][2]=0.f; sacc[j][3]=0.f; }
        #pragma unroll
        for (int ks=0; ks<4; ks++){
            #pragma unroll
            for (int nq=0; nq<4; nq++){
                u32 bfr[4];
                ldsm4(bfr, kbase + SWZ128((nq*16 + brow)*128 + (ks*16 + bkof)*2));
                mma16816h(sacc[nq*2+0], aq[ks], bfr[0], bfr[1]);
                mma16816h(sacc[nq*2+1], aq[ks], bfr[2], bfr[3]);
            }
        }

        if (kt >= 2*qt){
            #pragma unroll
            for (int j=0;j<8;j++){
                const int c = kt*64 + (j>>1)*16 + ((j&1)<<3) + ((lane&3)<<1);
                if (c   > rq)   sacc[j][0] = -1e30f;
                if (c+1 > rq)   sacc[j][1] = -1e30f;
                if (c   > rq+8) sacc[j][2] = -1e30f;
                if (c+1 > rq+8) sacc[j][3] = -1e30f;
            }
        }

        float mx0 = -1e30f, mx1 = -1e30f;
        #pragma unroll
        for (int j=0;j<8;j++){
            mx0 = fmaxf(mx0, fmaxf(sacc[j][0], sacc[j][1]));
            mx1 = fmaxf(mx1, fmaxf(sacc[j][2], sacc[j][3]));
        }
        mx0 = fmaxf(mx0, __shfl_xor_sync(0xffffffffu, mx0, 1));
        mx0 = fmaxf(mx0, __shfl_xor_sync(0xffffffffu, mx0, 2));
        mx1 = fmaxf(mx1, __shfl_xor_sync(0xffffffffu, mx1, 1));
        mx1 = fmaxf(mx1, __shfl_xor_sync(0xffffffffu, mx1, 2));
        const float mn0 = fmaxf(m0, mx0), mn1 = fmaxf(m1, mx1);
        const float cr0 = __expf(m0 - mn0), cr1 = __expf(m1 - mn1);
        m0 = mn0; m1 = mn1;
        float rs0 = 0.f, rs1 = 0.f;
        #pragma unroll
        for (int j=0;j<8;j++){
            sacc[j][0] = __expf(sacc[j][0] - mn0); rs0 += sacc[j][0];
            sacc[j][1] = __expf(sacc[j][1] - mn0); rs0 += sacc[j][1];
            sacc[j][2] = __expf(sacc[j][2] - mn1); rs1 += sacc[j][2];
            sacc[j][3] = __expf(sacc[j][3] - mn1); rs1 += sacc[j][3];
        }
        rs0 += __shfl_xor_sync(0xffffffffu, rs0, 1);
        rs0 += __shfl_xor_sync(0xffffffffu, rs0, 2);
        rs1 += __shfl_xor_sync(0xffffffffu, rs1, 1);
        rs1 += __shfl_xor_sync(0xffffffffu, rs1, 2);
        l0 = l0*cr0 + rs0;
        l1 = l1*cr1 + rs1;
        #pragma unroll
        for (int j=0;j<8;j++){
            oacc[j][0] *= cr0; oacc[j][1] *= cr0;
            oacc[j][2] *= cr1; oacc[j][3] *= cr1;
        }

        #pragma unroll
        for (int kc=0; kc<4; kc++){
            u32 ap[4];
            ap[0] = h2pack(sacc[2*kc  ][0], sacc[2*kc  ][1]);
            ap[1] = h2pack(sacc[2*kc  ][2], sacc[2*kc  ][3]);
            ap[2] = h2pack(sacc[2*kc+1][0], sacc[2*kc+1][1]);
            ap[3] = h2pack(sacc[2*kc+1][2], sacc[2*kc+1][3]);
            #pragma unroll
            for (int nq=0; nq<4; nq++){
                u32 bfr[4];
                ldsm4t(bfr, vbase + SWZ128((kc*16 + vrow)*128 + (nq*16 + vnof)*2));
                mma16816h(oacc[nq*2+0], ap, bfr[0], bfr[1]);
                mma16816h(oacc[nq*2+1], ap, bfr[2], bfr[3]);
            }
        }
        slot++; if (slot >= 3) slot = 0;
    }

    // ---- epilogue: normalize, write fp16 Aao [b*SEQ+t][2048]
    const float inv0 = 1.f / l0, inv1 = 1.f / l1;
    const int b = bh >> 5, h = bh & 31;
    const int t0 = qt*128 + wid*16 + (lane >> 2);
    __half* a0 = Aao + ((size_t)(b*SEQ + t0))*EMB + h*64;
    __half* a1 = a0 + 8*(size_t)EMB;
    #pragma unroll
    for (int j=0;j<8;j++){
        const int c = (j>>1)*16 + ((j&1)<<3) + ((lane&3)<<1);
        *(u32*)(a0 + c) = h2pack(oacc[j][0]*inv0, oacc[j][1]*inv0);
        *(u32*)(a1 + c) = h2pack(oacc[j][2]*inv1, oacc[j][3]*inv1);
    }
}

// =============================================================================
extern "C" void kernel_launch(void* const* d_in, const int* in_sizes, int n_in,
                              void* d_out, int out_size)
{
    (void)in_sizes; (void)n_in; (void)out_size;
    const float* x    = (const float*)d_in[0];
    const float* Wqkv = (const float*)d_in[1];
    const float* bqkv = (const float*)d_in[2];
    const float* Wout = (const float*)d_in[3];
    const float* bout = (const float*)d_in[4];
    float* out = (float*)d_out;

    __half *qh, *kh, *vh, *Ax, *Aao, *Bqkv, *Bout;
    float* rope;
    cudaGetSymbolAddress((void**)&qh,  g_qh);
    cudaGetSymbolAddress((void**)&kh,  g_kh);
    cudaGetSymbolAddress((void**)&vh,  g_vh);
    cudaGetSymbolAddress((void**)&Ax,   g_Ax);
    cudaGetSymbolAddress((void**)&Aao,  g_Aao);
    cudaGetSymbolAddress((void**)&Bqkv, g_Bqkv);
    cudaGetSymbolAddress((void**)&Bout, g_Bout);
    cudaGetSymbolAddress((void**)&rope, g_rope);

    cudaFuncSetAttribute(gemm_qkv_rope, cudaFuncAttributeMaxDynamicSharedMemorySize, GEMM_SMEM);
    cudaFuncSetAttribute(gemm_out,      cudaFuncAttributeMaxDynamicSharedMemorySize, GEMM_SMEM);
    cudaFuncSetAttribute(flash_hmma,    cudaFuncAttributeMaxDynamicSharedMemorySize, FA_SMEM);

    // 0) fused prep: weight transposes + x conversion + rope table (one launch)
    prep<<<PREP_TABLE, 256>>>(x, Wqkv, Wout, Ax, Bqkv, Bout, rope);

    // 1) QKV projection with fused bias + RoPE + scatter
    gemm_qkv_rope<<<dim3(N_QKV/256, BT/128), 512, GEMM_SMEM>>>(Ax, Bqkv, bqkv, rope, qh, kh, vh);

    // 2) causal flash attention (fp16 tensor cores, trans-V); writes fp16 Aao
    flash_hmma<<<dim3(SEQ/128, BATCH*NHEAD), 256, FA_SMEM>>>(qh, kh, vh, Aao);

    // 3) output projection (fp16 HMMA, fp32 output)
    gemm_out<<<dim3(EMB/256, BT/128), 512, GEMM_SMEM>>>(Aao, Bout, bout, out, EMB);
}

// round 16
// speedup vs baseline: 1.1503x; 1.0151x over previous
#include <cuda_runtime.h>
#include <cuda_fp16.h>
#include <cstdint>
#include <math.h>

typedef unsigned long long ull;
typedef unsigned int u32;

// ======================= problem constants =======================
#define BATCH   2
#define SEQ     2048
#define EMB     2048
#define NHEAD   32
#define HDIM    64
#define BT      (BATCH*SEQ)      // 4096
#define N_QKV   (3*EMB)          // 6144
#define KP      2048             // plain fp16 GEMM K

// ======================= scratch (device globals) ================
__device__ __half g_qh[(size_t)BATCH*NHEAD*SEQ*HDIM];  // [b,h,t,d] (rope, scaled)
__device__ __half g_kh[(size_t)BATCH*NHEAD*SEQ*HDIM];  // [b,h,t,d] (rope)
__device__ __half g_vh[(size_t)BATCH*NHEAD*SEQ*HDIM];  // [b,h,t,d]
__device__ __half g_Ax  [(size_t)BT * KP];             // x fp16
__device__ __half g_Aao [(size_t)BT * KP];             // attn-out fp16
__device__ __half g_Bqkv[(size_t)N_QKV * KP];          // Wqkv^T fp16
__device__ __half g_Bout[(size_t)EMB * KP];            // Wout^T fp16
__device__ float  g_rope[(size_t)SEQ * 32];            // [t][0:16)=cos, [t][16:32)=sin

// ======================= helpers =================================
__device__ __forceinline__ u32 smem_u32(const void* p){
    u32 a; asm("{ .reg .u64 t; cvta.to.shared.u64 t, %1; cvt.u32.u64 %0, t; }" : "=r"(a) : "l"(p));
    return a;
}
#define SWZ128(off) ((off) ^ (((off) >> 3) & 0x70))

__device__ __forceinline__ void cpasync16(u32 daddr, const void* gptr){
    asm volatile("cp.async.cg.shared.global [%0], [%1], 16;" :: "r"(daddr), "l"(gptr));
}
#define CP_COMMIT() asm volatile("cp.async.commit_group;")
#define CP_WAIT(n)  asm volatile("cp.async.wait_group %0;" :: "n"(n))

__device__ __forceinline__ void ldsm4(u32* r, u32 addr){
    asm volatile("ldmatrix.sync.aligned.m8n8.x4.shared.b16 {%0,%1,%2,%3}, [%4];"
        : "=r"(r[0]), "=r"(r[1]), "=r"(r[2]), "=r"(r[3]) : "r"(addr));
}
__device__ __forceinline__ void ldsm4t(u32* r, u32 addr){
    asm volatile("ldmatrix.sync.aligned.m8n8.x4.trans.shared.b16 {%0,%1,%2,%3}, [%4];"
        : "=r"(r[0]), "=r"(r[1]), "=r"(r[2]), "=r"(r[3]) : "r"(addr));
}
__device__ __forceinline__ void mma16816h(float* c, const u32* a, u32 b0, u32 b1){
    asm volatile("mma.sync.aligned.m16n8k16.row.col.f32.f16.f16.f32 "
        "{%0,%1,%2,%3}, {%4,%5,%6,%7}, {%8,%9}, {%0,%1,%2,%3};"
        : "+f"(c[0]), "+f"(c[1]), "+f"(c[2]), "+f"(c[3])
        : "r"(a[0]), "r"(a[1]), "r"(a[2]), "r"(a[3]), "r"(b0), "r"(b1));
}
__device__ __forceinline__ u32 h2pack(float a, float b){
    u32 r;
    asm("cvt.rn.f16x2.f32 %0, %2, %1;" : "=r"(r) : "f"(a), "f"(b));
    return r;
}

// =============================================================================
// Fused prep kernel (unchanged from round 15)
// =============================================================================
#define PREP_WQKV   3072
#define PREP_WOUT   4096
#define PREP_X      6144
#define PREP_TABLE  6272

__device__ __forceinline__ void convBT_tile(const float* __restrict__ W,
                                            __half* __restrict__ Bp,
                                            int N, int bid)
{
    __shared__ float tile[64][65];
    const int ntiles = N >> 6;
    const int k0 = (bid / ntiles) << 6;
    const int n0 = (bid % ntiles) << 6;
    const int tid = threadIdx.x;

    #pragma unroll
    for (int it=0; it<4; it++){
        const int slot = tid + it*256;
        const int r  = slot >> 4;
        const int c4 = (slot & 15) * 4;
        const float4 v = *(const float4*)(W + (size_t)(k0 + r)*N + n0 + c4);
        tile[r][c4+0] = v.x; tile[r][c4+1] = v.y;
        tile[r][c4+2] = v.z; tile[r][c4+3] = v.w;
    }
    __syncthreads();

    #pragma unroll
    for (int p=0; p<2; p++){
        const int task  = tid + p*256;
        const int chunk = task & 7;
        const int rn    = task >> 3;
        __half h[8];
        #pragma unroll
        for (int j=0; j<8; j++)
            h[j] = __float2half_rn(tile[chunk*8 + j][rn]);
        *(uint4*)(Bp + (size_t)(n0 + rn)*KP + k0 + chunk*8) = *(const uint4*)h;
    }
}

__global__ __launch_bounds__(256)
void prep(const float* __restrict__ x, const float* __restrict__ Wqkv,
          const float* __restrict__ Wout,
          __half* __restrict__ Ax, __half* __restrict__ Bqkv,
          __half* __restrict__ Bout, float* __restrict__ T)
{
    const int bid = blockIdx.x;
    const int tid = threadIdx.x;
    if (bid < PREP_WQKV){
        convBT_tile(Wqkv, Bqkv, N_QKV, bid);
    } else if (bid < PREP_WOUT){
        convBT_tile(Wout, Bout, EMB, bid - PREP_WQKV);
    } else if (bid < PREP_X){
        const size_t base = (size_t)(bid - PREP_WOUT) * 4096;
        #pragma unroll
        for (int it=0; it<4; it++){
            const size_t i = base + (size_t)(tid + it*256) * 4;
            const float4 v = *(const float4*)(x + i);
            __half h[4] = { __float2half_rn(v.x), __float2half_rn(v.y),
                            __float2half_rn(v.z), __float2half_rn(v.w) };
            *(ull*)(Ax + i) = *(const ull*)h;
        }
    } else {
        const int idx = (bid - PREP_X)*256 + tid;
        if (idx < SEQ*16){
            const int t = idx >> 4, i = idx & 15;
            const float invf = expf(-(float)i * (9.210340371976184f / 16.0f));
            float sn, cs; sincosf((float)t * invf, &sn, &cs);
            T[t*32 + i]      = cs;
            T[t*32 + 16 + i] = sn;
        }
    }
}

// =============================================================================
// GEMM mainloop (round-5 shape): 128x128 CTA, 8 warps (32x64), 2 CTAs/SM,
// 3-stage cp.async ring, GK=64.
// =============================================================================
#define GK 64
#define NC (KP/GK)              // 32
#define STAGE_A 16384
#define STAGE_B 16384
#define STAGE   (STAGE_A + STAGE_B)    // 32 KB
#define NSTG 3
#define GEMM_SMEM (NSTG*STAGE)         // 96 KB

#define GEMM_MAINLOOP(Aptr, Bptr)                                              \
    const __half* Ab = (Aptr) + (size_t)m0 * KP;                               \
    const __half* Bb = (Bptr) + (size_t)n0 * KP;                               \
    const int lr = tid >> 1;                                                   \
    const int lk = (tid & 1) * 4;                                              \
    auto load_stage = [&](int kc, u32 off){                                    \
        const __half* Ag = Ab + (size_t)lr*KP + kc*GK + lk*8;                  \
        const __half* Bg = Bb + (size_t)lr*KP + kc*GK + lk*8;                  \
        _Pragma("unroll")                                                      \
        for (int j=0;j<4;j++){                                                 \
            cpasync16(sb + off           + SWZ128(lr*128 + (lk+j)*16), Ag + j*8); \
            cpasync16(sb + off + STAGE_A + SWZ128(lr*128 + (lk+j)*16), Bg + j*8); \
        }                                                                      \
    };                                                                         \
    float acc[2][8][4];                                                        \
    _Pragma("unroll")                                                          \
    for (int a=0;a<2;a++)                                                      \
        _Pragma("unroll")                                                      \
        for (int b2=0;b2<8;b2++)                                               \
            _Pragma("unroll")                                                  \
            for (int c=0;c<4;c++) acc[a][b2][c] = 0.f;                         \
    load_stage(0, 0);       CP_COMMIT();                                       \
    load_stage(1, STAGE);   CP_COMMIT();                                       \
    const int arow = wm*32 + (lane & 15);                                      \
    const int akof = (lane >> 4) * 8;                                          \
    const int brow = wn*64 + ((lane >> 4) & 1)*8 + (lane & 7);                 \
    const int bkof = ((lane >> 3) & 1) * 8;                                    \
    int slot = 0;                                                              \
    for (int i=0; i<NC; i++){                                                  \
        CP_WAIT(1);                                                            \
        __syncthreads();                                                       \
        if (i+2 < NC){                                                         \
            int ns = slot + 2; if (ns >= NSTG) ns -= NSTG;                     \
            load_stage(i+2, (u32)ns * STAGE);                                  \
        }                                                                      \
        CP_COMMIT();                                                           \
        const u32 abase = sb + (u32)slot * STAGE;                              \
        const u32 bbase = abase + STAGE_A;                                     \
        _Pragma("unroll")                                                      \
        for (int ks=0; ks<4; ks++){                                            \
            const int k0 = ks*16;                                              \
            u32 afr[2][4];                                                     \
            _Pragma("unroll")                                                  \
            for (int mf=0; mf<2; mf++)                                         \
                ldsm4(afr[mf], abase + SWZ128((arow + mf*16)*128 + (k0 + akof)*2)); \
            u32 bfr[4][4];                                                     \
            _Pragma("unroll")                                                  \
            for (int nq=0; nq<4; nq++)                                         \
                ldsm4(bfr[nq], bbase + SWZ128((brow + nq*16)*128 + (k0 + bkof)*2)); \
            _Pragma("unroll")                                                  \
            for (int mf=0; mf<2; mf++)                                         \
                _Pragma("unroll")                                              \
                for (int nq=0; nq<4; nq++){                                    \
                    mma16816h(acc[mf][nq*2+0], afr[mf], bfr[nq][0], bfr[nq][1]); \
                    mma16816h(acc[mf][nq*2+1], afr[mf], bfr[nq][2], bfr[nq][3]); \
                }                                                              \
        }                                                                      \
        slot++; if (slot >= NSTG) slot = 0;                                    \
    }

// =============================================================================
// QKV GEMM with fused bias + RoPE + scatter to qh/kh/vh [b,h,t,d] fp16.
// 128x128 CTA: warp cols wn in {0,1}, each warp tile = one head.
// =============================================================================
__global__ __launch_bounds__(256, 2)
void gemm_qkv_rope(const __half* __restrict__ A,
                   const __half* __restrict__ B,
                   const float* __restrict__ bias,
                   const float* __restrict__ T,
                   __half* __restrict__ qh, __half* __restrict__ kh,
                   __half* __restrict__ vh)
{
    extern __shared__ char smem[];
    const u32 sb = smem_u32(smem);
    const int tid  = threadIdx.x;
    const int wid  = tid >> 5;
    const int lane = tid & 31;
    const int wm = wid & 3;
    const int wn = wid >> 2;
    const int m0 = blockIdx.y * 128;
    const int n0 = blockIdx.x * 128;

    GEMM_MAINLOOP(A, B)

    // ---- epilogue: bias + rope + scatter
    const int c0  = n0 + wn*64;
    const int seg = c0 >> 11;            // 0=q, 1=k, 2=v
    const int h   = (c0 >> 6) & 31;
    const float scale = (seg == 0) ? 0.125f : 1.0f;
    __half* dstbase = (seg == 0) ? qh : (seg == 1) ? kh : vh;

    #pragma unroll
    for (int mf=0; mf<2; mf++){
        const int r = m0 + wm*32 + mf*16 + (lane >> 2);
        const int b = r >> 11, t = r & 2047;
        float vv[8][4];
        #pragma unroll
        for (int nf=0; nf<8; nf++){
            const int c = c0 + nf*8 + (lane & 3)*2;
            const float b0 = bias[c], b1 = bias[c+1];
            vv[nf][0] = acc[mf][nf][0] + b0;
            vv[nf][1] = acc[mf][nf][1] + b1;
            vv[nf][2] = acc[mf][nf][2] + b0;
            vv[nf][3] = acc[mf][nf][3] + b1;
        }
        if (seg < 2){
            #pragma unroll
            for (int nf=0; nf<2; nf++){
                #pragma unroll
                for (int q=0; q<4; q++){
                    const int i  = nf*8 + (lane & 3)*2 + (q & 1);
                    const int tt = t + (q >> 1)*8;
                    const float cs = T[tt*32 + i], sn = T[tt*32 + 16 + i];
                    const float x1 = vv[nf][q], x2 = vv[nf+2][q];
                    vv[nf][q]   = x1*cs - x2*sn;
                    vv[nf+2][q] = x1*sn + x2*cs;
                }
            }
        }
        __half* dst = dstbase + ((size_t)(b*NHEAD + h)*SEQ + t)*HDIM;
        #pragma unroll
        for (int nf=0; nf<8; nf++){
            const int d = nf*8 + (lane & 3)*2;
            *(u32*)(dst + d)            = h2pack(vv[nf][0]*scale, vv[nf][1]*scale);
            *(u32*)(dst + 8*HDIM + d)   = h2pack(vv[nf][2]*scale, vv[nf][3]*scale);
        }
    }
}

// =============================================================================
// Output-projection GEMM (fp32 out + bias), 128x128 CTA.
// =============================================================================
__global__ __launch_bounds__(256, 2)
void gemm_out(const __half* __restrict__ A,
              const __half* __restrict__ B,
              const float* __restrict__ bias,
              float* __restrict__ C, int N)
{
    extern __shared__ char smem[];
    const u32 sb = smem_u32(smem);
    const int tid  = threadIdx.x;
    const int wid  = tid >> 5;
    const int lane = tid & 31;
    const int wm = wid & 3;
    const int wn = wid >> 2;
    const int m0 = blockIdx.y * 128;
    const int n0 = blockIdx.x * 128;

    GEMM_MAINLOOP(A, B)

    #pragma unroll
    for (int mf=0; mf<2; mf++){
        const int r = m0 + wm*32 + mf*16 + (lane >> 2);
        #pragma unroll
        for (int nf=0; nf<8; nf++){
            const int c = n0 + wn*64 + nf*8 + (lane & 3)*2;
            const float b0 = bias[c], b1 = bias[c+1];
            float* cp = C + (size_t)r*N + c;
            *(float2*)cp = make_float2(acc[mf][nf][0] + b0, acc[mf][nf][1] + b1);
            *(float2*)(cp + 8*(size_t)N) = make_float2(acc[mf][nf][2] + b0, acc[mf][nf][3] + b1);
        }
    }
}

// =============================================================================
// Flash attention, fp16 HMMA, causal. V [t][d] via trans-ldmatrix.
// 4-stage KV ring, 3 tiles of prefetch depth.
// =============================================================================
#define FA_KV   16384
#define FA_NSTG 4
#define FA_SMEM (16384 + FA_NSTG*FA_KV)   // 80 KB

__global__ __launch_bounds__(256, 2)
void flash_hmma(const __half* __restrict__ Qh, const __half* __restrict__ Kh,
                const __half* __restrict__ Vh, __half* __restrict__ Aao)
{
    extern __shared__ char smem[];
    const u32 sb = smem_u32(smem);
    const int tid = threadIdx.x, wid = tid >> 5, lane = tid & 31;
    const int qt = (int)gridDim.x - 1 - (int)blockIdx.x;   // heavy tiles first
    const int bh = blockIdx.y;
    const size_t base = (size_t)bh * SEQ * HDIM;
    const int nkt = 2*qt + 2;

    {
        const int r = tid >> 1;
        const int g = (tid & 1) * 4;
        const __half* Qg = Qh + base + (size_t)(qt*128 + r)*HDIM + g*8;
        #pragma unroll
        for (int j=0;j<4;j++)
            cpasync16(sb + SWZ128(r*128 + (g+j)*16), Qg + j*8);
    }
    const int kvr = tid >> 2;
    const int kvg = (tid & 3) * 2;
    auto load_kv = [&](int kt, u32 off){
        const __half* Kg = Kh + base + (size_t)(kt*64 + kvr)*HDIM + kvg*8;
        cpasync16(sb + off        + SWZ128(kvr*128 +  kvg   *16), Kg);
        cpasync16(sb + off        + SWZ128(kvr*128 + (kvg+1)*16), Kg + 8);
        const __half* Vg = Vh + base + (size_t)(kt*64 + kvr)*HDIM + kvg*8;
        cpasync16(sb + off + 8192 + SWZ128(kvr*128 +  kvg   *16), Vg);
        cpasync16(sb + off + 8192 + SWZ128(kvr*128 + (kvg+1)*16), Vg + 8);
    };

    // prologue: Q + kv0 in group0; kv1 group1; kv2 group2
    load_kv(0, 16384);                                CP_COMMIT();
    if (nkt > 1) load_kv(1, 16384 + FA_KV);           CP_COMMIT();
    if (nkt > 2) load_kv(2, 16384 + 2*FA_KV);         CP_COMMIT();

    CP_WAIT(2);
    __syncthreads();   // Q + kv0 ready

    u32 aq[4][4];
    {
        const int arow = wid*16 + (lane & 15);
        const int akof = (lane >> 4) * 8;
        #pragma unroll
        for (int ks=0; ks<4; ks++)
            ldsm4(aq[ks], sb + SWZ128(arow*128 + (ks*16 + akof)*2));
    }

    const int brow = ((lane >> 4) & 1)*8 + (lane & 7);
    const int bkof = ((lane >> 3) & 1) * 8;
    const int vrow = ((lane >> 3) & 1)*8 + (lane & 7);
    const int vnof = ((lane >> 4) & 1)*8;
    const int rq   = qt*128 + wid*16 + (lane >> 2);

    float oacc[8][4];
    #pragma unroll
    for (int j=0;j<8;j++){ oacc[j][0]=0.f; oacc[j][1]=0.f; oacc[j][2]=0.f; oacc[j][3]=0.f; }
    float m0 = -1e30f, m1 = -1e30f, l0 = 0.f, l1 = 0.f;

    int slot = 0;
    for (int kt = 0; kt < nkt; kt++){
        if (kt > 0){ CP_WAIT(2); __syncthreads(); }
        if (kt+3 < nkt){
            int ns = slot + 3; if (ns >= FA_NSTG) ns -= FA_NSTG;
            load_kv(kt+3, 16384 + (u32)ns*FA_KV);
        }
        CP_COMMIT();

        const u32 kbase = sb + 16384 + (u32)slot*FA_KV;
        const u32 vbase = kbase + 8192;

        float sacc[8][4];
        #pragma unroll
        for (int j=0;j<8;j++){ sacc[j][0]=0.f; sacc[j][1]=0.f; sacc[j][2]=0.f; sacc[j][3]=0.f; }
        #pragma unroll
        for (int ks=0; ks<4; ks++){
            #pragma unroll
            for (int nq=0; nq<4; nq++){
                u32 bfr[4];
                ldsm4(bfr, kbase + SWZ128((nq*16 + brow)*128 + (ks*16 + bkof)*2));
                mma16816h(sacc[nq*2+0], aq[ks], bfr[0], bfr[1]);
                mma16816h(sacc[nq*2+1], aq[ks], bfr[2], bfr[3]);
            }
        }

        if (kt >= 2*qt){
            #pragma unroll
            for (int j=0;j<8;j++){
                const int c = kt*64 + (j>>1)*16 + ((j&1)<<3) + ((lane&3)<<1);
                if (c   > rq)   sacc[j][0] = -1e30f;
                if (c+1 > rq)   sacc[j][1] = -1e30f;
                if (c   > rq+8) sacc[j][2] = -1e30f;
                if (c+1 > rq+8) sacc[j][3] = -1e30f;
            }
        }

        float mx0 = -1e30f, mx1 = -1e30f;
        #pragma unroll
        for (int j=0;j<8;j++){
            mx0 = fmaxf(mx0, fmaxf(sacc[j][0], sacc[j][1]));
            mx1 = fmaxf(mx1, fmaxf(sacc[j][2], sacc[j][3]));
        }
        mx0 = fmaxf(mx0, __shfl_xor_sync(0xffffffffu, mx0, 1));
        mx0 = fmaxf(mx0, __shfl_xor_sync(0xffffffffu, mx0, 2));
        mx1 = fmaxf(mx1, __shfl_xor_sync(0xffffffffu, mx1, 1));
        mx1 = fmaxf(mx1, __shfl_xor_sync(0xffffffffu, mx1, 2));
        const float mn0 = fmaxf(m0, mx0), mn1 = fmaxf(m1, mx1);
        const float cr0 = __expf(m0 - mn0), cr1 = __expf(m1 - mn1);
        m0 = mn0; m1 = mn1;
        float rs0 = 0.f, rs1 = 0.f;
        #pragma unroll
        for (int j=0;j<8;j++){
            sacc[j][0] = __expf(sacc[j][0] - mn0); rs0 += sacc[j][0];
            sacc[j][1] = __expf(sacc[j][1] - mn0); rs0 += sacc[j][1];
            sacc[j][2] = __expf(sacc[j][2] - mn1); rs1 += sacc[j][2];
            sacc[j][3] = __expf(sacc[j][3] - mn1); rs1 += sacc[j][3];
        }
        rs0 += __shfl_xor_sync(0xffffffffu, rs0, 1);
        rs0 += __shfl_xor_sync(0xffffffffu, rs0, 2);
        rs1 += __shfl_xor_sync(0xffffffffu, rs1, 1);
        rs1 += __shfl_xor_sync(0xffffffffu, rs1, 2);
        l0 = l0*cr0 + rs0;
        l1 = l1*cr1 + rs1;
        #pragma unroll
        for (int j=0;j<8;j++){
            oacc[j][0] *= cr0; oacc[j][1] *= cr0;
            oacc[j][2] *= cr1; oacc[j][3] *= cr1;
        }

        #pragma unroll
        for (int kc=0; kc<4; kc++){
            u32 ap[4];
            ap[0] = h2pack(sacc[2*kc  ][0], sacc[2*kc  ][1]);
            ap[1] = h2pack(sacc[2*kc  ][2], sacc[2*kc  ][3]);
            ap[2] = h2pack(sacc[2*kc+1][0], sacc[2*kc+1][1]);
            ap[3] = h2pack(sacc[2*kc+1][2], sacc[2*kc+1][3]);
            #pragma unroll
            for (int nq=0; nq<4; nq++){
                u32 bfr[4];
                ldsm4t(bfr, vbase + SWZ128((kc*16 + vrow)*128 + (nq*16 + vnof)*2));
                mma16816h(oacc[nq*2+0], ap, bfr[0], bfr[1]);
                mma16816h(oacc[nq*2+1], ap, bfr[2], bfr[3]);
            }
        }
        slot++; if (slot >= FA_NSTG) slot = 0;
    }

    // ---- epilogue: normalize, write fp16 Aao [b*SEQ+t][2048]
    const float inv0 = 1.f / l0, inv1 = 1.f / l1;
    const int b = bh >> 5, h = bh & 31;
    const int t0 = qt*128 + wid*16 + (lane >> 2);
    __half* a0 = Aao + ((size_t)(b*SEQ + t0))*EMB + h*64;
    __half* a1 = a0 + 8*(size_t)EMB;
    #pragma unroll
    for (int j=0;j<8;j++){
        const int c = (j>>1)*16 + ((j&1)<<3) + ((lane&3)<<1);
        *(u32*)(a0 + c) = h2pack(oacc[j][0]*inv0, oacc[j][1]*inv0);
        *(u32*)(a1 + c) = h2pack(oacc[j][2]*inv1, oacc[j][3]*inv1);
    }
}

// =============================================================================
extern "C" void kernel_launch(void* const* d_in, const int* in_sizes, int n_in,
                              void* d_out, int out_size)
{
    (void)in_sizes; (void)n_in; (void)out_size;
    const float* x    = (const float*)d_in[0];
    const float* Wqkv = (const float*)d_in[1];
    const float* bqkv = (const float*)d_in[2];
    const float* Wout = (const float*)d_in[3];
    const float* bout = (const float*)d_in[4];
    float* out = (float*)d_out;

    __half *qh, *kh, *vh, *Ax, *Aao, *Bqkv, *Bout;
    float* rope;
    cudaGetSymbolAddress((void**)&qh,  g_qh);
    cudaGetSymbolAddress((void**)&kh,  g_kh);
    cudaGetSymbolAddress((void**)&vh,  g_vh);
    cudaGetSymbolAddress((void**)&Ax,   g_Ax);
    cudaGetSymbolAddress((void**)&Aao,  g_Aao);
    cudaGetSymbolAddress((void**)&Bqkv, g_Bqkv);
    cudaGetSymbolAddress((void**)&Bout, g_Bout);
    cudaGetSymbolAddress((void**)&rope, g_rope);

    cudaFuncSetAttribute(gemm_qkv_rope, cudaFuncAttributeMaxDynamicSharedMemorySize, GEMM_SMEM);
    cudaFuncSetAttribute(gemm_out,      cudaFuncAttributeMaxDynamicSharedMemorySize, GEMM_SMEM);
    cudaFuncSetAttribute(flash_hmma,    cudaFuncAttributeMaxDynamicSharedMemorySize, FA_SMEM);

    // 0) fused prep
    prep<<<PREP_TABLE, 256>>>(x, Wqkv, Wout, Ax, Bqkv, Bout, rope);

    // 1) QKV projection with fused bias + RoPE + scatter (128x128 tiles)
    gemm_qkv_rope<<<dim3(N_QKV/128, BT/128), 256, GEMM_SMEM>>>(Ax, Bqkv, bqkv, rope, qh, kh, vh);

    // 2) causal flash attention (4-stage ring)
    flash_hmma<<<dim3(SEQ/128, BATCH*NHEAD), 256, FA_SMEM>>>(qh, kh, vh, Aao);

    // 3) output projection (128x128 tiles)
    gemm_out<<<dim3(EMB/128, BT/128), 256, GEMM_SMEM>>>(Aao, Bout, bout, out, EMB);
}

// round 17
// speedup vs baseline: 1.1599x; 1.0084x over previous
#include <cuda_runtime.h>
#include <cuda_fp16.h>
#include <cstdint>
#include <math.h>

typedef unsigned long long ull;
typedef unsigned int u32;

// ======================= problem constants =======================
#define BATCH   2
#define SEQ     2048
#define EMB     2048
#define NHEAD   32
#define HDIM    64
#define BT      (BATCH*SEQ)      // 4096
#define N_QKV   (3*EMB)          // 6144
#define KP      2048             // plain fp16 GEMM K

// ======================= scratch (device globals) ================
__device__ __half g_qh[(size_t)BATCH*NHEAD*SEQ*HDIM];  // [b,h,t,d] (rope, scaled)
__device__ __half g_kh[(size_t)BATCH*NHEAD*SEQ*HDIM];  // [b,h,t,d] (rope)
__device__ __half g_vh[(size_t)BATCH*NHEAD*SEQ*HDIM];  // [b,h,t,d]
__device__ __half g_Ax  [(size_t)BT * KP];             // x fp16
__device__ __half g_Aao [(size_t)BT * KP];             // attn-out fp16
__device__ __half g_Bqkv[(size_t)N_QKV * KP];          // Wqkv^T fp16
__device__ __half g_Bout[(size_t)EMB * KP];            // Wout^T fp16
__device__ float  g_rope[(size_t)SEQ * 32];            // [t][0:16)=cos, [t][16:32)=sin

// ======================= helpers =================================
__device__ __forceinline__ u32 smem_u32(const void* p){
    u32 a; asm("{ .reg .u64 t; cvta.to.shared.u64 t, %1; cvt.u32.u64 %0, t; }" : "=r"(a) : "l"(p));
    return a;
}
#define SWZ128(off) ((off) ^ (((off) >> 3) & 0x70))

__device__ __forceinline__ void cpasync16(u32 daddr, const void* gptr){
    asm volatile("cp.async.cg.shared.global [%0], [%1], 16;" :: "r"(daddr), "l"(gptr));
}
#define CP_COMMIT() asm volatile("cp.async.commit_group;")
#define CP_WAIT(n)  asm volatile("cp.async.wait_group %0;" :: "n"(n))

__device__ __forceinline__ void ldsm4(u32* r, u32 addr){
    asm volatile("ldmatrix.sync.aligned.m8n8.x4.shared.b16 {%0,%1,%2,%3}, [%4];"
        : "=r"(r[0]), "=r"(r[1]), "=r"(r[2]), "=r"(r[3]) : "r"(addr));
}
__device__ __forceinline__ void ldsm4t(u32* r, u32 addr){
    asm volatile("ldmatrix.sync.aligned.m8n8.x4.trans.shared.b16 {%0,%1,%2,%3}, [%4];"
        : "=r"(r[0]), "=r"(r[1]), "=r"(r[2]), "=r"(r[3]) : "r"(addr));
}
__device__ __forceinline__ void mma16816h(float* c, const u32* a, u32 b0, u32 b1){
    asm volatile("mma.sync.aligned.m16n8k16.row.col.f32.f16.f16.f32 "
        "{%0,%1,%2,%3}, {%4,%5,%6,%7}, {%8,%9}, {%0,%1,%2,%3};"
        : "+f"(c[0]), "+f"(c[1]), "+f"(c[2]), "+f"(c[3])
        : "r"(a[0]), "r"(a[1]), "r"(a[2]), "r"(a[3]), "r"(b0), "r"(b1));
}
__device__ __forceinline__ u32 h2pack(float a, float b){
    u32 r;
    asm("cvt.rn.f16x2.f32 %0, %2, %1;" : "=r"(r) : "f"(a), "f"(b));
    return r;
}

// =============================================================================
// Fused prep kernel (unchanged)
// =============================================================================
#define PREP_WQKV   3072
#define PREP_WOUT   4096
#define PREP_X      6144
#define PREP_TABLE  6272

__device__ __forceinline__ void convBT_tile(const float* __restrict__ W,
                                            __half* __restrict__ Bp,
                                            int N, int bid)
{
    __shared__ float tile[64][65];
    const int ntiles = N >> 6;
    const int k0 = (bid / ntiles) << 6;
    const int n0 = (bid % ntiles) << 6;
    const int tid = threadIdx.x;

    #pragma unroll
    for (int it=0; it<4; it++){
        const int slot = tid + it*256;
        const int r  = slot >> 4;
        const int c4 = (slot & 15) * 4;
        const float4 v = *(const float4*)(W + (size_t)(k0 + r)*N + n0 + c4);
        tile[r][c4+0] = v.x; tile[r][c4+1] = v.y;
        tile[r][c4+2] = v.z; tile[r][c4+3] = v.w;
    }
    __syncthreads();

    #pragma unroll
    for (int p=0; p<2; p++){
        const int task  = tid + p*256;
        const int chunk = task & 7;
        const int rn    = task >> 3;
        __half h[8];
        #pragma unroll
        for (int j=0; j<8; j++)
            h[j] = __float2half_rn(tile[chunk*8 + j][rn]);
        *(uint4*)(Bp + (size_t)(n0 + rn)*KP + k0 + chunk*8) = *(const uint4*)h;
    }
}

__global__ __launch_bounds__(256)
void prep(const float* __restrict__ x, const float* __restrict__ Wqkv,
          const float* __restrict__ Wout,
          __half* __restrict__ Ax, __half* __restrict__ Bqkv,
          __half* __restrict__ Bout, float* __restrict__ T)
{
    const int bid = blockIdx.x;
    const int tid = threadIdx.x;
    if (bid < PREP_WQKV){
        convBT_tile(Wqkv, Bqkv, N_QKV, bid);
    } else if (bid < PREP_WOUT){
        convBT_tile(Wout, Bout, EMB, bid - PREP_WQKV);
    } else if (bid < PREP_X){
        const size_t base = (size_t)(bid - PREP_WOUT) * 4096;
        #pragma unroll
        for (int it=0; it<4; it++){
            const size_t i = base + (size_t)(tid + it*256) * 4;
            const float4 v = *(const float4*)(x + i);
            __half h[4] = { __float2half_rn(v.x), __float2half_rn(v.y),
                            __float2half_rn(v.z), __float2half_rn(v.w) };
            *(ull*)(Ax + i) = *(const ull*)h;
        }
    } else {
        const int idx = (bid - PREP_X)*256 + tid;
        if (idx < SEQ*16){
            const int t = idx >> 4, i = idx & 15;
            const float invf = expf(-(float)i * (9.210340371976184f / 16.0f));
            float sn, cs; sincosf((float)t * invf, &sn, &cs);
            T[t*32 + i]      = cs;
            T[t*32 + 16 + i] = sn;
        }
    }
}

// =============================================================================
// GEMM mainloop (round-15 shape): 128x256 CTA, 16 warps 4x4 (warp 32x64),
// 1 CTA/SM, 3-stage cp.async ring, GK=64.
// =============================================================================
#define GK 64
#define NC (KP/GK)              // 32
#define STAGE_A 16384
#define STAGE_B 32768
#define STAGE   (STAGE_A + STAGE_B)
#define NSTG 3
#define GEMM_SMEM (NSTG*STAGE)

#define GEMM_MAINLOOP(Aptr, Bptr)                                              \
    const __half* Ab = (Aptr) + (size_t)m0 * KP;                               \
    const __half* Bb = (Bptr) + (size_t)n0 * KP;                               \
    const int alr = tid >> 2;                                                  \
    const int alk = (tid & 3) * 2;                                             \
    const int blr = tid >> 1;                                                  \
    const int blk = (tid & 1) * 4;                                             \
    auto load_stage = [&](int kc, u32 off){                                    \
        const __half* Ag = Ab + (size_t)alr*KP + kc*GK + alk*8;                \
        _Pragma("unroll")                                                      \
        for (int j=0;j<2;j++)                                                  \
            cpasync16(sb + off + SWZ128(alr*128 + (alk+j)*16), Ag + j*8);      \
        const __half* Bg = Bb + (size_t)blr*KP + kc*GK + blk*8;                \
        _Pragma("unroll")                                                      \
        for (int j=0;j<4;j++)                                                  \
            cpasync16(sb + off + STAGE_A + SWZ128(blr*128 + (blk+j)*16), Bg + j*8); \
    };                                                                         \
    float acc[2][8][4];                                                        \
    _Pragma("unroll")                                                          \
    for (int a=0;a<2;a++)                                                      \
        _Pragma("unroll")                                                      \
        for (int b2=0;b2<8;b2++)                                               \
            _Pragma("unroll")                                                  \
            for (int c=0;c<4;c++) acc[a][b2][c] = 0.f;                         \
    load_stage(0, 0);       CP_COMMIT();                                       \
    load_stage(1, STAGE);   CP_COMMIT();                                       \
    const int arow = wm*32 + (lane & 15);                                      \
    const int akof = (lane >> 4) * 8;                                          \
    const int brow = wn*64 + ((lane >> 4) & 1)*8 + (lane & 7);                 \
    const int bkof = ((lane >> 3) & 1) * 8;                                    \
    int slot = 0;                                                              \
    for (int i=0; i<NC; i++){                                                  \
        CP_WAIT(1);                                                            \
        __syncthreads();                                                       \
        if (i+2 < NC){                                                         \
            int ns = slot + 2; if (ns >= NSTG) ns -= NSTG;                     \
            load_stage(i+2, (u32)ns * STAGE);                                  \
        }                                                                      \
        CP_COMMIT();                                                           \
        const u32 abase = sb + (u32)slot * STAGE;                              \
        const u32 bbase = abase + STAGE_A;                                     \
        _Pragma("unroll")                                                      \
        for (int ks=0; ks<4; ks++){                                            \
            const int k0 = ks*16;                                              \
            u32 afr[2][4];                                                     \
            _Pragma("unroll")                                                  \
            for (int mf=0; mf<2; mf++)                                         \
                ldsm4(afr[mf], abase + SWZ128((arow + mf*16)*128 + (k0 + akof)*2)); \
            u32 bfr[4][4];                                                     \
            _Pragma("unroll")                                                  \
            for (int nq=0; nq<4; nq++)                                         \
                ldsm4(bfr[nq], bbase + SWZ128((brow + nq*16)*128 + (k0 + bkof)*2)); \
            _Pragma("unroll")                                                  \
            for (int mf=0; mf<2; mf++)                                         \
                _Pragma("unroll")                                              \
                for (int nq=0; nq<4; nq++){                                    \
                    mma16816h(acc[mf][nq*2+0], afr[mf], bfr[nq][0], bfr[nq][1]); \
                    mma16816h(acc[mf][nq*2+1], afr[mf], bfr[nq][2], bfr[nq][3]); \
                }                                                              \
        }                                                                      \
        slot++; if (slot >= NSTG) slot = 0;                                    \
    }

// =============================================================================
// QKV GEMM with fused bias + RoPE + scatter to qh/kh/vh [b,h,t,d] fp16.
// =============================================================================
__global__ __launch_bounds__(512, 1)
void gemm_qkv_rope(const __half* __restrict__ A,
                   const __half* __restrict__ B,
                   const float* __restrict__ bias,
                   const float* __restrict__ T,
                   __half* __restrict__ qh, __half* __restrict__ kh,
                   __half* __restrict__ vh)
{
    extern __shared__ char smem[];
    const u32 sb = smem_u32(smem);
    const int tid  = threadIdx.x;
    const int wid  = tid >> 5;
    const int lane = tid & 31;
    const int wm = wid & 3;
    const int wn = wid >> 2;
    const int m0 = blockIdx.y * 128;
    const int n0 = blockIdx.x * 256;

    GEMM_MAINLOOP(A, B)

    // ---- epilogue: bias + rope + scatter
    const int c0  = n0 + wn*64;          // 64-aligned: one head
    const int seg = c0 >> 11;            // 0=q, 1=k, 2=v
    const int h   = (c0 >> 6) & 31;
    const float scale = (seg == 0) ? 0.125f : 1.0f;
    __half* dstbase = (seg == 0) ? qh : (seg == 1) ? kh : vh;

    #pragma unroll
    for (int mf=0; mf<2; mf++){
        const int r = m0 + wm*32 + mf*16 + (lane >> 2);
        const int b = r >> 11, t = r & 2047;
        float vv[8][4];
        #pragma unroll
        for (int nf=0; nf<8; nf++){
            const int c = c0 + nf*8 + (lane & 3)*2;
            const float b0 = bias[c], b1 = bias[c+1];
            vv[nf][0] = acc[mf][nf][0] + b0;
            vv[nf][1] = acc[mf][nf][1] + b1;
            vv[nf][2] = acc[mf][nf][2] + b0;
            vv[nf][3] = acc[mf][nf][3] + b1;
        }
        if (seg < 2){
            #pragma unroll
            for (int nf=0; nf<2; nf++){
                #pragma unroll
                for (int q=0; q<4; q++){
                    const int i  = nf*8 + (lane & 3)*2 + (q & 1);
                    const int tt = t + (q >> 1)*8;
                    const float cs = T[tt*32 + i], sn = T[tt*32 + 16 + i];
                    const float x1 = vv[nf][q], x2 = vv[nf+2][q];
                    vv[nf][q]   = x1*cs - x2*sn;
                    vv[nf+2][q] = x1*sn + x2*cs;
                }
            }
        }
        __half* dst = dstbase + ((size_t)(b*NHEAD + h)*SEQ + t)*HDIM;
        #pragma unroll
        for (int nf=0; nf<8; nf++){
            const int d = nf*8 + (lane & 3)*2;
            *(u32*)(dst + d)            = h2pack(vv[nf][0]*scale, vv[nf][1]*scale);
            *(u32*)(dst + 8*HDIM + d)   = h2pack(vv[nf][2]*scale, vv[nf][3]*scale);
        }
    }
}

// =============================================================================
// Output-projection GEMM (fp32 out + bias).
// =============================================================================
__global__ __launch_bounds__(512, 1)
void gemm_out(const __half* __restrict__ A,
              const __half* __restrict__ B,
              const float* __restrict__ bias,
              float* __restrict__ C, int N)
{
    extern __shared__ char smem[];
    const u32 sb = smem_u32(smem);
    const int tid  = threadIdx.x;
    const int wid  = tid >> 5;
    const int lane = tid & 31;
    const int wm = wid & 3;
    const int wn = wid >> 2;
    const int m0 = blockIdx.y * 128;
    const int n0 = blockIdx.x * 256;

    GEMM_MAINLOOP(A, B)

    #pragma unroll
    for (int mf=0; mf<2; mf++){
        const int r = m0 + wm*32 + mf*16 + (lane >> 2);
        #pragma unroll
        for (int nf=0; nf<8; nf++){
            const int c = n0 + wn*64 + nf*8 + (lane & 3)*2;
            const float b0 = bias[c], b1 = bias[c+1];
            float* cp = C + (size_t)r*N + c;
            *(float2*)cp = make_float2(acc[mf][nf][0] + b0, acc[mf][nf][1] + b1);
            *(float2*)(cp + 8*(size_t)N) = make_float2(acc[mf][nf][2] + b0, acc[mf][nf][3] + b1);
        }
    }
}

// =============================================================================
// Flash attention, fp16 HMMA, causal. V [t][d] via trans-ldmatrix.
// 4-stage KV ring, 3 tiles of prefetch depth.
// =============================================================================
#define FA_KV   16384
#define FA_NSTG 4
#define FA_SMEM (16384 + FA_NSTG*FA_KV)   // 80 KB

__global__ __launch_bounds__(256, 2)
void flash_hmma(const __half* __restrict__ Qh, const __half* __restrict__ Kh,
                const __half* __restrict__ Vh, __half* __restrict__ Aao)
{
    extern __shared__ char smem[];
    const u32 sb = smem_u32(smem);
    const int tid = threadIdx.x, wid = tid >> 5, lane = tid & 31;
    const int qt = (int)gridDim.x - 1 - (int)blockIdx.x;   // heavy tiles first
    const int bh = blockIdx.y;
    const size_t base = (size_t)bh * SEQ * HDIM;
    const int nkt = 2*qt + 2;

    {
        const int r = tid >> 1;
        const int g = (tid & 1) * 4;
        const __half* Qg = Qh + base + (size_t)(qt*128 + r)*HDIM + g*8;
        #pragma unroll
        for (int j=0;j<4;j++)
            cpasync16(sb + SWZ128(r*128 + (g+j)*16), Qg + j*8);
    }
    const int kvr = tid >> 2;
    const int kvg = (tid & 3) * 2;
    auto load_kv = [&](int kt, u32 off){
        const __half* Kg = Kh + base + (size_t)(kt*64 + kvr)*HDIM + kvg*8;
        cpasync16(sb + off        + SWZ128(kvr*128 +  kvg   *16), Kg);
        cpasync16(sb + off        + SWZ128(kvr*128 + (kvg+1)*16), Kg + 8);
        const __half* Vg = Vh + base + (size_t)(kt*64 + kvr)*HDIM + kvg*8;
        cpasync16(sb + off + 8192 + SWZ128(kvr*128 +  kvg   *16), Vg);
        cpasync16(sb + off + 8192 + SWZ128(kvr*128 + (kvg+1)*16), Vg + 8);
    };

    load_kv(0, 16384);                                CP_COMMIT();
    if (nkt > 1) load_kv(1, 16384 + FA_KV);           CP_COMMIT();
    if (nkt > 2) load_kv(2, 16384 + 2*FA_KV);         CP_COMMIT();

    CP_WAIT(2);
    __syncthreads();

    u32 aq[4][4];
    {
        const int arow = wid*16 + (lane & 15);
        const int akof = (lane >> 4) * 8;
        #pragma unroll
        for (int ks=0; ks<4; ks++)
            ldsm4(aq[ks], sb + SWZ128(arow*128 + (ks*16 + akof)*2));
    }

    const int brow = ((lane >> 4) & 1)*8 + (lane & 7);
    const int bkof = ((lane >> 3) & 1) * 8;
    const int vrow = ((lane >> 3) & 1)*8 + (lane & 7);
    const int vnof = ((lane >> 4) & 1)*8;
    const int rq   = qt*128 + wid*16 + (lane >> 2);

    float oacc[8][4];
    #pragma unroll
    for (int j=0;j<8;j++){ oacc[j][0]=0.f; oacc[j][1]=0.f; oacc[j][2]=0.f; oacc[j][3]=0.f; }
    float m0 = -1e30f, m1 = -1e30f, l0 = 0.f, l1 = 0.f;

    int slot = 0;
    for (int kt = 0; kt < nkt; kt++){
        if (kt > 0){ CP_WAIT(2); __syncthreads(); }
        if (kt+3 < nkt){
            int ns = slot + 3; if (ns >= FA_NSTG) ns -= FA_NSTG;
            load_kv(kt+3, 16384 + (u32)ns*FA_KV);
        }
        CP_COMMIT();

        const u32 kbase = sb + 16384 + (u32)slot*FA_KV;
        const u32 vbase = kbase + 8192;

        float sacc[8][4];
        #pragma unroll
        for (int j=0;j<8;j++){ sacc[j][0]=0.f; sacc[j][1]=0.f; sacc[j][2]=0.f; sacc[j][3]=0.f; }
        #pragma unroll
        for (int ks=0; ks<4; ks++){
            #pragma unroll
            for (int nq=0; nq<4; nq++){
                u32 bfr[4];
                ldsm4(bfr, kbase + SWZ128((nq*16 + brow)*128 + (ks*16 + bkof)*2));
                mma16816h(sacc[nq*2+0], aq[ks], bfr[0], bfr[1]);
                mma16816h(sacc[nq*2+1], aq[ks], bfr[2], bfr[3]);
            }
        }

        if (kt >= 2*qt){
            #pragma unroll
            for (int j=0;j<8;j++){
                const int c = kt*64 + (j>>1)*16 + ((j&1)<<3) + ((lane&3)<<1);
                if (c   > rq)   sacc[j][0] = -1e30f;
                if (c+1 > rq)   sacc[j][1] = -1e30f;
                if (c   > rq+8) sacc[j][2] = -1e30f;
                if (c+1 > rq+8) sacc[j][3] = -1e30f;
            }
        }

        float mx0 = -1e30f, mx1 = -1e30f;
        #pragma unroll
        for (int j=0;j<8;j++){
            mx0 = fmaxf(mx0, fmaxf(sacc[j][0], sacc[j][1]));
            mx1 = fmaxf(mx1, fmaxf(sacc[j][2], sacc[j][3]));
        }
        mx0 = fmaxf(mx0, __shfl_xor_sync(0xffffffffu, mx0, 1));
        mx0 = fmaxf(mx0, __shfl_xor_sync(0xffffffffu, mx0, 2));
        mx1 = fmaxf(mx1, __shfl_xor_sync(0xffffffffu, mx1, 1));
        mx1 = fmaxf(mx1, __shfl_xor_sync(0xffffffffu, mx1, 2));
        const float mn0 = fmaxf(m0, mx0), mn1 = fmaxf(m1, mx1);
        const float cr0 = __expf(m0 - mn0), cr1 = __expf(m1 - mn1);
        m0 = mn0; m1 = mn1;
        float rs0 = 0.f, rs1 = 0.f;
        #pragma unroll
        for (int j=0;j<8;j++){
            sacc[j][0] = __expf(sacc[j][0] - mn0); rs0 += sacc[j][0];
            sacc[j][1] = __expf(sacc[j][1] - mn0); rs0 += sacc[j][1];
            sacc[j][2] = __expf(sacc[j][2] - mn1); rs1 += sacc[j][2];
            sacc[j][3] = __expf(sacc[j][3] - mn1); rs1 += sacc[j][3];
        }
        rs0 += __shfl_xor_sync(0xffffffffu, rs0, 1);
        rs0 += __shfl_xor_sync(0xffffffffu, rs0, 2);
        rs1 += __shfl_xor_sync(0xffffffffu, rs1, 1);
        rs1 += __shfl_xor_sync(0xffffffffu, rs1, 2);
        l0 = l0*cr0 + rs0;
        l1 = l1*cr1 + rs1;
        #pragma unroll
        for (int j=0;j<8;j++){
            oacc[j][0] *= cr0; oacc[j][1] *= cr0;
            oacc[j][2] *= cr1; oacc[j][3] *= cr1;
        }

        #pragma unroll
        for (int kc=0; kc<4; kc++){
            u32 ap[4];
            ap[0] = h2pack(sacc[2*kc  ][0], sacc[2*kc  ][1]);
            ap[1] = h2pack(sacc[2*kc  ][2], sacc[2*kc  ][3]);
            ap[2] = h2pack(sacc[2*kc+1][0], sacc[2*kc+1][1]);
            ap[3] = h2pack(sacc[2*kc+1][2], sacc[2*kc+1][3]);
            #pragma unroll
            for (int nq=0; nq<4; nq++){
                u32 bfr[4];
                ldsm4t(bfr, vbase + SWZ128((kc*16 + vrow)*128 + (nq*16 + vnof)*2));
                mma16816h(oacc[nq*2+0], ap, bfr[0], bfr[1]);
                mma16816h(oacc[nq*2+1], ap, bfr[2], bfr[3]);
            }
        }
        slot++; if (slot >= FA_NSTG) slot = 0;
    }

    // ---- epilogue: normalize, write fp16 Aao [b*SEQ+t][2048]
    const float inv0 = 1.f / l0, inv1 = 1.f / l1;
    const int b = bh >> 5, h = bh & 31;
    const int t0 = qt*128 + wid*16 + (lane >> 2);
    __half* a0 = Aao + ((size_t)(b*SEQ + t0))*EMB + h*64;
    __half* a1 = a0 + 8*(size_t)EMB;
    #pragma unroll
    for (int j=0;j<8;j++){
        const int c = (j>>1)*16 + ((j&1)<<3) + ((lane&3)<<1);
        *(u32*)(a0 + c) = h2pack(oacc[j][0]*inv0, oacc[j][1]*inv0);
        *(u32*)(a1 + c) = h2pack(oacc[j][2]*inv1, oacc[j][3]*inv1);
    }
}

// =============================================================================
extern "C" void kernel_launch(void* const* d_in, const int* in_sizes, int n_in,
                              void* d_out, int out_size)
{
    (void)in_sizes; (void)n_in; (void)out_size;
    const float* x    = (const float*)d_in[0];
    const float* Wqkv = (const float*)d_in[1];
    const float* bqkv = (const float*)d_in[2];
    const float* Wout = (const float*)d_in[3];
    const float* bout = (const float*)d_in[4];
    float* out = (float*)d_out;

    __half *qh, *kh, *vh, *Ax, *Aao, *Bqkv, *Bout;
    float* rope;
    cudaGetSymbolAddress((void**)&qh,  g_qh);
    cudaGetSymbolAddress((void**)&kh,  g_kh);
    cudaGetSymbolAddress((void**)&vh,  g_vh);
    cudaGetSymbolAddress((void**)&Ax,   g_Ax);
    cudaGetSymbolAddress((void**)&Aao,  g_Aao);
    cudaGetSymbolAddress((void**)&Bqkv, g_Bqkv);
    cudaGetSymbolAddress((void**)&Bout, g_Bout);
    cudaGetSymbolAddress((void**)&rope, g_rope);

    cudaFuncSetAttribute(gemm_qkv_rope, cudaFuncAttributeMaxDynamicSharedMemorySize, GEMM_SMEM);
    cudaFuncSetAttribute(gemm_out,      cudaFuncAttributeMaxDynamicSharedMemorySize, GEMM_SMEM);
    cudaFuncSetAttribute(flash_hmma,    cudaFuncAttributeMaxDynamicSharedMemorySize, FA_SMEM);

    // 0) fused prep
    prep<<<PREP_TABLE, 256>>>(x, Wqkv, Wout, Ax, Bqkv, Bout, rope);

    // 1) QKV projection with fused bias + RoPE + scatter (128x256 tiles)
    gemm_qkv_rope<<<dim3(N_QKV/256, BT/128), 512, GEMM_SMEM>>>(Ax, Bqkv, bqkv, rope, qh, kh, vh);

    // 2) causal flash attention (4-stage ring)
    flash_hmma<<<dim3(SEQ/128, BATCH*NHEAD), 256, FA_SMEM>>>(qh, kh, vh, Aao);

    // 3) output projection (128x256 tiles)
    gemm_out<<<dim3(EMB/256, BT/128), 512, GEMM_SMEM>>>(Aao, Bout, bout, out, EMB);
}